// round 14
// baseline (speedup 1.0000x reference)
#include <cuda_runtime.h>
#include <cuda_fp16.h>
#include <math.h>
#include <stdint.h>

#define NN    50000
#define EIN   800000
#define ETOT  850000
#define GMAX  64
#define NBLK  ((NN + 1023) / 1024)

// ---------------- scratch (device globals; zero-initialized at load) -------
__device__ int    g_deg[NN];
__device__ int    g_off[NN + 1];
__device__ int    g_fill[NN];
__device__ int    g_src[ETOT];
__device__ int    g_bsum[64];
__device__ int    g_bpre[64];
__device__ float  g_es[NN * 8];
__device__ float  g_ed[NN * 8];
__device__ __align__(16) __half g_h16[NN * 512];   // GEMM output h (fp16)
__device__ __align__(16) __half g_a16[NN * 512];   // agg output (fp16)
__device__ __align__(16) __half g_x16[NN * 128];   // fp16 x
__device__ __align__(16) __half g_w16[294912];     // fp16 W1..W4
__device__ float  g_pool[GMAX * 512];
__device__ float  g_cnt[GMAX];

// ---------------- operand conversion (x + W1..W4 -> fp16, one kernel) ------
#define X4   (NN * 128 / 4)
#define W4T  (294912 / 4)
__global__ void k_round_all(const float* __restrict__ x,
                            const float* __restrict__ w1, const float* __restrict__ w2,
                            const float* __restrict__ w3, const float* __restrict__ w4) {
    int i = blockIdx.x * blockDim.x + threadIdx.x;
    const float4* s;
    uint2* d;
    if (i < X4) {
        s = (const float4*)x + i;
        d = (uint2*)g_x16 + i;
    } else {
        int j = i - X4;
        if (j >= W4T) return;
        d = (uint2*)g_w16 + j;
        if      (j < 16384) s = (const float4*)w1 + j;
        else if (j < 49152) s = (const float4*)w2 + (j - 16384);
        else if (j < 57344) s = (const float4*)w3 + (j - 49152);
        else                s = (const float4*)w4 + (j - 57344);
    }
    float4 v = *s;
    __half2 h01 = __floats2half2_rn(v.x, v.y);
    __half2 h23 = __floats2half2_rn(v.z, v.w);
    uint2 o;
    *(__half2*)&o.x = h01;
    *(__half2*)&o.y = h23;
    *d = o;
}

// ---------------- CSR build --------------------------------------------------
__global__ void k_count(const int* __restrict__ ei) {
    int e = blockIdx.x * blockDim.x + threadIdx.x;
    if (e >= ETOT) return;
    int dst = (e < EIN) ? ei[EIN + e] : (e - EIN);
    atomicAdd(&g_deg[dst], 1);
}

__global__ void k_scan1() {
    __shared__ int wsum[32];
    int b = blockIdx.x, tid = threadIdx.x;
    int idx = b * 1024 + tid;
    int v = (idx < NN) ? g_deg[idx] : 0;
    int x = v;
    #pragma unroll
    for (int off = 1; off < 32; off <<= 1) {
        int y = __shfl_up_sync(0xffffffffu, x, off);
        if ((tid & 31) >= off) x += y;
    }
    if ((tid & 31) == 31) wsum[tid >> 5] = x;
    __syncthreads();
    if (tid < 32) {
        int w = wsum[tid];
        #pragma unroll
        for (int off = 1; off < 32; off <<= 1) {
            int y = __shfl_up_sync(0xffffffffu, w, off);
            if (tid >= off) w += y;
        }
        wsum[tid] = w;
    }
    __syncthreads();
    int incl = x + ((tid >= 32) ? wsum[(tid >> 5) - 1] : 0);
    if (idx < NN) g_off[idx] = incl - v;
    if (tid == 1023) g_bsum[b] = incl;
}

__global__ void k_scan2() {
    int tid = threadIdx.x;
    __shared__ int ws[2];
    int v = (tid < NBLK) ? g_bsum[tid] : 0;
    int x = v;
    #pragma unroll
    for (int off = 1; off < 32; off <<= 1) {
        int y = __shfl_up_sync(0xffffffffu, x, off);
        if ((tid & 31) >= off) x += y;
    }
    if ((tid & 31) == 31) ws[tid >> 5] = x;
    __syncthreads();
    int incl = x + ((tid >= 32) ? ws[0] : 0);
    if (tid < NBLK) g_bpre[tid] = incl - v;
    if (tid == NBLK - 1) g_off[NN] = incl;
}

__global__ void k_scan3() {
    int idx = blockIdx.x * 1024 + threadIdx.x;
    if (idx < NN) g_off[idx] += g_bpre[blockIdx.x];
}

__global__ void k_fill(const int* __restrict__ ei) {
    int e = blockIdx.x * blockDim.x + threadIdx.x;
    if (e >= ETOT) return;
    int src, dst;
    if (e < EIN) { src = ei[e]; dst = ei[EIN + e]; }
    else         { src = e - EIN; dst = e - EIN; }
    int pos = g_off[dst] + atomicAdd(&g_fill[dst], 1);
    g_src[pos] = src;
}

// ---------------- fp16 HMMA GEMM (3-stage cp.async) + attn epilogue ---------
#define SMSH   40
#define STAGEH (128 * SMSH)

__device__ __forceinline__ void cpa16(uint32_t dst, const void* src, bool p) {
    int sz = p ? 16 : 0;
    asm volatile("cp.async.cg.shared.global [%0], [%1], 16, %2;"
                 :: "r"(dst), "l"(src), "r"(sz));
}

__global__ __launch_bounds__(256, 2)
void k_gemm_tc(const __half* __restrict__ Ain, const __half* __restrict__ B,
               const float* __restrict__ as_, const float* __restrict__ ad_,
               int M, int N, int K, int C) {
    extern __shared__ char smraw[];
    __half* hsm = (__half*)smraw;
    const __half* A = Ain ? Ain : g_a16;

    const int tid  = threadIdx.x;
    const int lane = tid & 31;
    const int wid  = tid >> 5;
    const int gid  = lane >> 2;
    const int tg   = lane & 3;
    const int wm   = (wid >> 2) * 64;
    const int wn   = (wid & 3) * 32;

    const int bm = blockIdx.y * 128;
    const int bn = blockIdx.x * 128;

    const int r0 = tid >> 2;
    const int kq = (tid & 3) * 8;

    const int am0 = bm + r0, am1 = bm + r0 + 64;
    const bool p0 = am0 < M, p1 = am1 < M;
    const __half* arow0 = A + (size_t)(p0 ? am0 : 0) * K + kq;
    const __half* arow1 = A + (size_t)(p1 ? am1 : 0) * K + kq;
    const __half* brow0 = B + (size_t)(bn + r0) * K + kq;
    const __half* brow1 = B + (size_t)(bn + r0 + 64) * K + kq;

    uint32_t sm_base = (uint32_t)__cvta_generic_to_shared(hsm) + (r0 * SMSH + kq) * 2;
    const uint32_t stg   = STAGEH * 2;
    const uint32_t boff  = 3 * stg;
    const uint32_t half_ = 64 * SMSH * 2;

    float acc[4][4][4];
    #pragma unroll
    for (int mt = 0; mt < 4; mt++)
        #pragma unroll
        for (int nt = 0; nt < 4; nt++)
            #pragma unroll
            for (int i = 0; i < 4; i++) acc[mt][nt][i] = 0.f;

    const int KC = K >> 5;

    auto issue = [&](int kc) {
        int buf = kc % 3;
        int ko = kc * 32;
        cpa16(sm_base + buf * stg,                arow0 + ko, p0);
        cpa16(sm_base + buf * stg + half_,        arow1 + ko, p1);
        cpa16(sm_base + boff + buf * stg,         brow0 + ko, true);
        cpa16(sm_base + boff + buf * stg + half_, brow1 + ko, true);
        asm volatile("cp.async.commit_group;");
    };

    issue(0);
    issue(1);

    for (int kc = 0; kc < KC; kc++) {
        if (kc + 1 < KC) asm volatile("cp.async.wait_group 1;");
        else             asm volatile("cp.async.wait_group 0;");
        __syncthreads();
        if (kc + 2 < KC) issue(kc + 2);

        const __half* as = hsm + (kc % 3) * STAGEH;
        const __half* bs = hsm + 3 * STAGEH + (kc % 3) * STAGEH;
        #pragma unroll
        for (int s = 0; s < 2; s++) {
            int kl = s * 16;
            uint32_t af[4][4], bf[4][2];
            #pragma unroll
            for (int mt = 0; mt < 4; mt++) {
                int m = wm + mt * 16 + gid;
                af[mt][0] = *(const uint32_t*)&as[m * SMSH + kl + 2 * tg];
                af[mt][1] = *(const uint32_t*)&as[(m + 8) * SMSH + kl + 2 * tg];
                af[mt][2] = *(const uint32_t*)&as[m * SMSH + kl + 8 + 2 * tg];
                af[mt][3] = *(const uint32_t*)&as[(m + 8) * SMSH + kl + 8 + 2 * tg];
            }
            #pragma unroll
            for (int nt = 0; nt < 4; nt++) {
                int n = wn + nt * 8 + gid;
                bf[nt][0] = *(const uint32_t*)&bs[n * SMSH + kl + 2 * tg];
                bf[nt][1] = *(const uint32_t*)&bs[n * SMSH + kl + 8 + 2 * tg];
            }
            #pragma unroll
            for (int mt = 0; mt < 4; mt++)
                #pragma unroll
                for (int nt = 0; nt < 4; nt++) {
                    asm volatile(
                        "mma.sync.aligned.m16n8k16.row.col.f32.f16.f16.f32 "
                        "{%0,%1,%2,%3}, {%4,%5,%6,%7}, {%8,%9}, {%0,%1,%2,%3};"
                        : "+f"(acc[mt][nt][0]), "+f"(acc[mt][nt][1]),
                          "+f"(acc[mt][nt][2]), "+f"(acc[mt][nt][3])
                        : "r"(af[mt][0]), "r"(af[mt][1]), "r"(af[mt][2]), "r"(af[mt][3]),
                          "r"(bf[nt][0]), "r"(bf[nt][1]));
                }
        }
    }

    // ---- epilogue 1: store h as fp16 ----
    #pragma unroll
    for (int mt = 0; mt < 4; mt++) {
        int gm0 = bm + wm + mt * 16 + gid;
        int gm1 = gm0 + 8;
        #pragma unroll
        for (int nt = 0; nt < 4; nt++) {
            int gn = bn + wn + nt * 8 + tg * 2;
            if (gm0 < M)
                *(__half2*)(g_h16 + (size_t)gm0 * N + gn) =
                    __floats2half2_rn(acc[mt][nt][0], acc[mt][nt][1]);
            if (gm1 < M)
                *(__half2*)(g_h16 + (size_t)gm1 * N + gn) =
                    __floats2half2_rn(acc[mt][nt][2], acc[mt][nt][3]);
        }
    }

    // ---- epilogue 2: es/ed via smem reduction, direct store ----
    const int NH = 128 / C;
    float* red = (float*)smraw;
    __syncthreads();
    for (int i = tid; i < 128 * NH * 2; i += 256) red[i] = 0.f;
    __syncthreads();

    float av[4][2], dv[4][2];
    #pragma unroll
    for (int nt = 0; nt < 4; nt++) {
        int gc = bn + wn + nt * 8 + tg * 2;
        av[nt][0] = __ldg(as_ + gc);  av[nt][1] = __ldg(as_ + gc + 1);
        dv[nt][0] = __ldg(ad_ + gc);  dv[nt][1] = __ldg(ad_ + gc + 1);
    }
    const bool two = (C == 16);
    const int hl0 = wn / C;
    #pragma unroll
    for (int mt = 0; mt < 4; mt++) {
        #pragma unroll
        for (int hh = 0; hh < 2; hh++) {
            int rl = wm + mt * 16 + gid + hh * 8;
            float pes[2] = {0.f, 0.f}, ped[2] = {0.f, 0.f};
            #pragma unroll
            for (int nt = 0; nt < 4; nt++) {
                int sp = two ? (nt >> 1) : 0;
                float a0 = acc[mt][nt][hh * 2 + 0];
                float a1 = acc[mt][nt][hh * 2 + 1];
                pes[sp] += a0 * av[nt][0] + a1 * av[nt][1];
                ped[sp] += a0 * dv[nt][0] + a1 * dv[nt][1];
            }
            #pragma unroll
            for (int off = 1; off <= 2; off <<= 1) {
                pes[0] += __shfl_xor_sync(0xffffffffu, pes[0], off);
                ped[0] += __shfl_xor_sync(0xffffffffu, ped[0], off);
                pes[1] += __shfl_xor_sync(0xffffffffu, pes[1], off);
                ped[1] += __shfl_xor_sync(0xffffffffu, ped[1], off);
            }
            if (tg == 0) {
                atomicAdd(&red[rl * NH + hl0], pes[0]);
                atomicAdd(&red[128 * NH + rl * NH + hl0], ped[0]);
                if (two) {
                    atomicAdd(&red[rl * NH + hl0 + 1], pes[1]);
                    atomicAdd(&red[128 * NH + rl * NH + hl0 + 1], ped[1]);
                }
            }
        }
    }
    __syncthreads();
    const int hbase = bn / C;
    for (int i = tid; i < 128 * NH; i += 256) {
        int rl = i / NH, hl = i % NH;
        int row = bm + rl;
        if (row < M) {
            g_es[row * 8 + hbase + hl] = red[i];
            g_ed[row * 8 + hbase + hl] = red[128 * NH + i];
        }
    }
}

// ---------------- fused softmax + aggregation (LDG.128, layers 0,1,3) --------
template <int LOG2C, bool ELU, int LOG2S>
__global__ void k_agg4(const float* __restrict__ bias) {
    int gw = (blockIdx.x * blockDim.x + threadIdx.x) >> 5;
    int node = gw >> LOG2S;
    if (node >= NN) return;
    int part = gw & ((1 << LOG2S) - 1);
    const int lane = threadIdx.x & 31;
    const int Fout = 256 << LOG2S;
    const int base = part * 256;
    const int f = base + lane * 8;
    const int head = f >> LOG2C;
    const int ehead = lane & 7;
    const float edv = g_ed[node * 8 + ehead];
    int beg = g_off[node], end = g_off[node + 1];

    float acc[8];
    #pragma unroll
    for (int j = 0; j < 8; j++) acc[j] = 0.f;
    float sm = 0.f;

    int i = beg;
    for (; i + 4 <= end; i += 4) {
        int s0 = g_src[i],     s1 = g_src[i + 1];
        int s2 = g_src[i + 2], s3 = g_src[i + 3];
        int sel = lane >> 3;
        int ss = (sel == 0) ? s0 : (sel == 1) ? s1 : (sel == 2) ? s2 : s3;
        float e = __ldg(&g_es[ss * 8 + ehead]) + edv;
        e = e > 0.f ? e : 0.2f * e;
        float aw = __expf(e);
        sm += aw;
        uint4 u0 = __ldg((const uint4*)(g_h16 + (size_t)s0 * Fout + f));
        uint4 u1 = __ldg((const uint4*)(g_h16 + (size_t)s1 * Fout + f));
        uint4 u2 = __ldg((const uint4*)(g_h16 + (size_t)s2 * Fout + f));
        uint4 u3 = __ldg((const uint4*)(g_h16 + (size_t)s3 * Fout + f));
        float al0 = __shfl_sync(0xffffffffu, aw, head);
        float al1 = __shfl_sync(0xffffffffu, aw, 8 + head);
        float al2 = __shfl_sync(0xffffffffu, aw, 16 + head);
        float al3 = __shfl_sync(0xffffffffu, aw, 24 + head);
        const uint32_t* w0 = (const uint32_t*)&u0;
        const uint32_t* w1 = (const uint32_t*)&u1;
        const uint32_t* w2 = (const uint32_t*)&u2;
        const uint32_t* w3 = (const uint32_t*)&u3;
        #pragma unroll
        for (int q = 0; q < 4; q++) {
            float2 v0 = __half22float2(*(const __half2*)&w0[q]);
            float2 v1 = __half22float2(*(const __half2*)&w1[q]);
            float2 v2 = __half22float2(*(const __half2*)&w2[q]);
            float2 v3 = __half22float2(*(const __half2*)&w3[q]);
            acc[q*2+0] = fmaf(al0, v0.x, fmaf(al1, v1.x,
                          fmaf(al2, v2.x, fmaf(al3, v3.x, acc[q*2+0]))));
            acc[q*2+1] = fmaf(al0, v0.y, fmaf(al1, v1.y,
                          fmaf(al2, v2.y, fmaf(al3, v3.y, acc[q*2+1]))));
        }
    }
    for (; i < end; i++) {
        int s0 = g_src[i];
        float a0 = 0.f;
        if (lane < 8) {
            float e = __ldg(&g_es[s0 * 8 + ehead]) + edv;
            e = e > 0.f ? e : 0.2f * e;
            a0 = __expf(e);
        }
        sm += a0;
        float al0 = __shfl_sync(0xffffffffu, a0, head);
        uint4 u0 = __ldg((const uint4*)(g_h16 + (size_t)s0 * Fout + f));
        const uint32_t* w0 = (const uint32_t*)&u0;
        #pragma unroll
        for (int q = 0; q < 4; q++) {
            float2 v0 = __half22float2(*(const __half2*)&w0[q]);
            acc[q*2+0] = fmaf(al0, v0.x, acc[q*2+0]);
            acc[q*2+1] = fmaf(al0, v0.y, acc[q*2+1]);
        }
    }

    sm += __shfl_xor_sync(0xffffffffu, sm, 8);
    sm += __shfl_xor_sync(0xffffffffu, sm, 16);
    float inv = 1.f / __shfl_sync(0xffffffffu, sm, head);

    float4 b0 = __ldg((const float4*)(bias + f));
    float4 b1 = __ldg((const float4*)(bias + f + 4));
    float bb[8] = {b0.x, b0.y, b0.z, b0.w, b1.x, b1.y, b1.z, b1.w};
    uint4 o;
    uint32_t* ow = (uint32_t*)&o;
    #pragma unroll
    for (int q = 0; q < 4; q++) {
        float v0 = fmaf(acc[q*2+0], inv, bb[q*2+0]);
        float v1 = fmaf(acc[q*2+1], inv, bb[q*2+1]);
        if (ELU) {
            v0 = v0 > 0.f ? v0 : expm1f(v0);
            v1 = v1 > 0.f ? v1 : expm1f(v1);
        }
        __half2 h = __floats2half2_rn(v0, v1);
        ow[q] = *(uint32_t*)&h;
    }
    __stcs((uint4*)(g_a16 + (size_t)node * Fout + f), o);
}

// ---------------- fused softmax + aggregation (uint2, layer 2) ---------------
template <bool ELU>
__global__ void k_agg2(const float* __restrict__ bias) {
    int node = (blockIdx.x * blockDim.x + threadIdx.x) >> 5;
    if (node >= NN) return;
    const int lane = threadIdx.x & 31;
    const int Fout = 128;
    const int f = lane * 4;
    const int head = f >> 4;
    const int ehead = lane & 7;
    const float edv = g_ed[node * 8 + ehead];
    int beg = g_off[node], end = g_off[node + 1];

    float4 acc = make_float4(0.f, 0.f, 0.f, 0.f);
    float sm = 0.f;

    int i = beg;
    for (; i + 4 <= end; i += 4) {
        int s0 = g_src[i],     s1 = g_src[i + 1];
        int s2 = g_src[i + 2], s3 = g_src[i + 3];
        int sel = lane >> 3;
        int ss = (sel == 0) ? s0 : (sel == 1) ? s1 : (sel == 2) ? s2 : s3;
        float e = __ldg(&g_es[ss * 8 + ehead]) + edv;
        e = e > 0.f ? e : 0.2f * e;
        float aw = __expf(e);
        sm += aw;
        uint2 u0 = __ldg((const uint2*)(g_h16 + (size_t)s0 * Fout + f));
        uint2 u1 = __ldg((const uint2*)(g_h16 + (size_t)s1 * Fout + f));
        uint2 u2 = __ldg((const uint2*)(g_h16 + (size_t)s2 * Fout + f));
        uint2 u3 = __ldg((const uint2*)(g_h16 + (size_t)s3 * Fout + f));
        float al0 = __shfl_sync(0xffffffffu, aw, head);
        float al1 = __shfl_sync(0xffffffffu, aw, 8 + head);
        float al2 = __shfl_sync(0xffffffffu, aw, 16 + head);
        float al3 = __shfl_sync(0xffffffffu, aw, 24 + head);
        float2 lo0 = __half22float2(*(__half2*)&u0.x);
        float2 hi0 = __half22float2(*(__half2*)&u0.y);
        float2 lo1 = __half22float2(*(__half2*)&u1.x);
        float2 hi1 = __half22float2(*(__half2*)&u1.y);
        float2 lo2 = __half22float2(*(__half2*)&u2.x);
        float2 hi2 = __half22float2(*(__half2*)&u2.y);
        float2 lo3 = __half22float2(*(__half2*)&u3.x);
        float2 hi3 = __half22float2(*(__half2*)&u3.y);
        acc.x = fmaf(al0, lo0.x, fmaf(al1, lo1.x, fmaf(al2, lo2.x, fmaf(al3, lo3.x, acc.x))));
        acc.y = fmaf(al0, lo0.y, fmaf(al1, lo1.y, fmaf(al2, lo2.y, fmaf(al3, lo3.y, acc.y))));
        acc.z = fmaf(al0, hi0.x, fmaf(al1, hi1.x, fmaf(al2, hi2.x, fmaf(al3, hi3.x, acc.z))));
        acc.w = fmaf(al0, hi0.y, fmaf(al1, hi1.y, fmaf(al2, hi2.y, fmaf(al3, hi3.y, acc.w))));
    }
    for (; i < end; i++) {
        int s0 = g_src[i];
        float a0 = 0.f;
        if (lane < 8) {
            float e = __ldg(&g_es[s0 * 8 + ehead]) + edv;
            e = e > 0.f ? e : 0.2f * e;
            a0 = __expf(e);
        }
        sm += a0;
        float al0 = __shfl_sync(0xffffffffu, a0, head);
        uint2 u0 = __ldg((const uint2*)(g_h16 + (size_t)s0 * Fout + f));
        float2 lo0 = __half22float2(*(__half2*)&u0.x);
        float2 hi0 = __half22float2(*(__half2*)&u0.y);
        acc.x = fmaf(al0, lo0.x, acc.x);
        acc.y = fmaf(al0, lo0.y, acc.y);
        acc.z = fmaf(al0, hi0.x, acc.z);
        acc.w = fmaf(al0, hi0.y, acc.w);
    }

    sm += __shfl_xor_sync(0xffffffffu, sm, 8);
    sm += __shfl_xor_sync(0xffffffffu, sm, 16);
    float inv = 1.f / __shfl_sync(0xffffffffu, sm, head);

    float4 b4 = __ldg((const float4*)(bias + f));
    float v0 = fmaf(acc.x, inv, b4.x);
    float v1 = fmaf(acc.y, inv, b4.y);
    float v2 = fmaf(acc.z, inv, b4.z);
    float v3 = fmaf(acc.w, inv, b4.w);
    if (ELU) {
        v0 = v0 > 0.f ? v0 : expm1f(v0);
        v1 = v1 > 0.f ? v1 : expm1f(v1);
        v2 = v2 > 0.f ? v2 : expm1f(v2);
        v3 = v3 > 0.f ? v3 : expm1f(v3);
    }
    __half2 h01 = __floats2half2_rn(v0, v1);
    __half2 h23 = __floats2half2_rn(v2, v3);
    uint2 o;
    *(__half2*)&o.x = h01;
    *(__half2*)&o.y = h23;
    __stcs((uint2*)(g_a16 + (size_t)node * Fout + f), o);
}

// ---------------- pooling (init also clears CSR scratch) ---------------------
__global__ void k_pool_init() {
    int i = blockIdx.x * blockDim.x + threadIdx.x;
    if (i < GMAX * 512) g_pool[i] = 0.f;
    if (i < GMAX) g_cnt[i] = 0.f;
    if (i < NN) { g_deg[i] = 0; g_fill[i] = 0; }
}

__global__ void k_pool(const int* __restrict__ batch) {
    int f = threadIdx.x;
    int n0 = blockIdx.x * 512;
    int n1 = n0 + 512; if (n1 > NN) n1 = NN;
    if (n0 >= NN) return;
    float acc = 0.f;
    int cur = __ldg(&batch[n0]);
    float cnt = 0.f;
    for (int n = n0; n < n1; n++) {
        int b = __ldg(&batch[n]);
        if (b != cur) {
            atomicAdd(&g_pool[cur * 512 + f], acc);
            if (f == 0) atomicAdd(&g_cnt[cur], cnt);
            acc = 0.f; cnt = 0.f; cur = b;
        }
        acc += __half2float(g_a16[(size_t)n * 512 + f]);
        cnt += 1.f;
    }
    atomicAdd(&g_pool[cur * 512 + f], acc);
    if (f == 0) atomicAdd(&g_cnt[cur], cnt);
}

// ---------------- merged MLP head (single block) ------------------------------
__global__ void k_mlp(const float* __restrict__ lw1, const float* __restrict__ lb1,
                      const float* __restrict__ lw2, const float* __restrict__ lb2,
                      float* __restrict__ out) {
    __shared__ float smlp[GMAX * 32];
    int tid = threadIdx.x;   // 1024
    for (int t = tid; t < GMAX * 32; t += 1024) {
        int g = t >> 5, j = t & 31;
        float inv = 1.f / fmaxf(g_cnt[g], 1.f);
        const float* pp = g_pool + g * 512;
        const float* wp = lw1 + j * 512;
        float s = 0.f;
        for (int k = 0; k < 512; k++) s += pp[k] * __ldg(wp + k);
        s = s * inv + __ldg(lb1 + j);
        smlp[t] = s > 0.f ? s : expm1f(s);
    }
    __syncthreads();
    if (tid < GMAX * 2) {
        int g = tid >> 1, o = tid & 1;
        const float* mp = smlp + g * 32;
        const float* wp = lw2 + o * 32;
        float s = 0.f;
        #pragma unroll
        for (int k = 0; k < 32; k++) s += mp[k] * __ldg(wp + k);
        out[tid] = s + __ldg(lb2 + o);
    }
}

// ---------------- launch -----------------------------------------------------
#define GEMM_SMEM (6 * STAGEH * 2)   // 61440 bytes

extern "C" void kernel_launch(void* const* d_in, const int* in_sizes, int n_in,
                              void* d_out, int out_size) {
    const float* x     = (const float*)d_in[0];
    const int*   ei    = (const int*)  d_in[1];
    const int*   batch = (const int*)  d_in[2];
    const float *W[4], *as_[4], *ad_[4], *bb[4];
    for (int l = 0; l < 4; l++) {
        W[l]   = (const float*)d_in[3 + l * 4];
        as_[l] = (const float*)d_in[4 + l * 4];
        ad_[l] = (const float*)d_in[5 + l * 4];
        bb[l]  = (const float*)d_in[6 + l * 4];
    }
    const float* lw1 = (const float*)d_in[19];
    const float* lb1 = (const float*)d_in[20];
    const float* lw2 = (const float*)d_in[21];
    const float* lb2 = (const float*)d_in[22];
    float* out = (float*)d_out;

    cudaFuncSetAttribute(k_gemm_tc, cudaFuncAttributeMaxDynamicSharedMemorySize,
                         GEMM_SMEM);

    const int woff[4] = {0, 65536, 196608, 229376};
    __half* w16_base;
    cudaGetSymbolAddress((void**)&w16_base, g_w16);
    __half* x16_base;
    cudaGetSymbolAddress((void**)&x16_base, g_x16);

    const int Fo[4]  = {512, 256, 128, 512};
    const int Cc[4]  = {64, 32, 16, 64};
    const int Fin[4] = {128, 512, 256, 128};

    k_round_all<<<(X4 + W4T + 255) / 256, 256>>>(x, W[0], W[1], W[2], W[3]);
    k_count<<<(ETOT + 255) / 256, 256>>>(ei);
    {
        dim3 gg(Fo[0] / 128, (NN + 127) / 128);
        k_gemm_tc<<<gg, 256, GEMM_SMEM>>>(x16_base, w16_base + woff[0],
                                          as_[0], ad_[0], NN, Fo[0], Fin[0], Cc[0]);
    }
    k_scan1<<<NBLK, 1024>>>();
    k_scan2<<<1, 64>>>();
    k_scan3<<<NBLK, 1024>>>();
    k_fill<<<(ETOT + 255) / 256, 256>>>(ei);

    {
        int nb = (NN * 2 * 32 + 255) / 256;
        k_agg4<6, true, 1><<<nb, 256>>>(bb[0]);
    }

    for (int l = 1; l < 4; l++) {
        dim3 gg(Fo[l] / 128, (NN + 127) / 128);
        k_gemm_tc<<<gg, 256, GEMM_SMEM>>>(nullptr, w16_base + woff[l],
                                          as_[l], ad_[l], NN, Fo[l], Fin[l], Cc[l]);
        if (l == 1) {
            int nb = (NN * 32 + 255) / 256;
            k_agg4<5, true, 0><<<nb, 256>>>(bb[l]);
        } else if (l == 2) {
            int nb = (NN * 32 + 255) / 256;
            k_agg2<true><<<nb, 256>>>(bb[l]);
        } else {
            int nb = (NN * 2 * 32 + 255) / 256;
            k_agg4<6, false, 1><<<nb, 256>>>(bb[l]);
        }
    }

    k_pool_init<<<(NN + 255) / 256, 256>>>();
    k_pool<<<(NN + 511) / 512, 512>>>(batch);
    k_mlp<<<1, 1024>>>(lw1, lb1, lw2, lb2, out);
}

// round 15
// speedup vs baseline: 1.6961x; 1.6961x over previous
#include <cuda_runtime.h>
#include <cuda_fp16.h>
#include <math.h>
#include <stdint.h>

#define NN    50000
#define EIN   800000
#define ETOT  850000
#define GMAX  64
#define NBLK  ((NN + 1023) / 1024)

// ---------------- scratch (device globals; zero-initialized at load) -------
__device__ int    g_deg[NN];
__device__ int    g_off[NN + 1];
__device__ int    g_fill[NN];
__device__ int    g_src[ETOT];
__device__ int    g_bsum[64];
__device__ int    g_bpre[64];
__device__ float  g_es[NN * 8];
__device__ float  g_ed[NN * 8];
__device__ __align__(16) __half g_h16[NN * 512];   // GEMM output h (fp16)
__device__ __align__(16) __half g_a16[NN * 512];   // agg output (fp16)
__device__ __align__(16) __half g_x16[NN * 128];   // fp16 x
__device__ __align__(16) __half g_w16[294912];     // fp16 W1..W4
__device__ float  g_pool[GMAX * 512];
__device__ float  g_cnt[GMAX];
__device__ float  g_mlp[GMAX * 32];

// ---------------- operand conversion (x + W1..W4 -> fp16, one kernel) ------
#define X4   (NN * 128 / 4)
#define W4T  (294912 / 4)
__global__ void k_round_all(const float* __restrict__ x,
                            const float* __restrict__ w1, const float* __restrict__ w2,
                            const float* __restrict__ w3, const float* __restrict__ w4) {
    int i = blockIdx.x * blockDim.x + threadIdx.x;
    const float4* s;
    uint2* d;
    if (i < X4) {
        s = (const float4*)x + i;
        d = (uint2*)g_x16 + i;
    } else {
        int j = i - X4;
        if (j >= W4T) return;
        d = (uint2*)g_w16 + j;
        if      (j < 16384) s = (const float4*)w1 + j;
        else if (j < 49152) s = (const float4*)w2 + (j - 16384);
        else if (j < 57344) s = (const float4*)w3 + (j - 49152);
        else                s = (const float4*)w4 + (j - 57344);
    }
    float4 v = *s;
    __half2 h01 = __floats2half2_rn(v.x, v.y);
    __half2 h23 = __floats2half2_rn(v.z, v.w);
    uint2 o;
    *(__half2*)&o.x = h01;
    *(__half2*)&o.y = h23;
    *d = o;
}

// ---------------- CSR build --------------------------------------------------
__global__ void k_count(const int* __restrict__ ei) {
    int e = blockIdx.x * blockDim.x + threadIdx.x;
    if (e >= ETOT) return;
    int dst = (e < EIN) ? ei[EIN + e] : (e - EIN);
    atomicAdd(&g_deg[dst], 1);
}

__global__ void k_scan1() {
    __shared__ int wsum[32];
    int b = blockIdx.x, tid = threadIdx.x;
    int idx = b * 1024 + tid;
    int v = (idx < NN) ? g_deg[idx] : 0;
    int x = v;
    #pragma unroll
    for (int off = 1; off < 32; off <<= 1) {
        int y = __shfl_up_sync(0xffffffffu, x, off);
        if ((tid & 31) >= off) x += y;
    }
    if ((tid & 31) == 31) wsum[tid >> 5] = x;
    __syncthreads();
    if (tid < 32) {
        int w = wsum[tid];
        #pragma unroll
        for (int off = 1; off < 32; off <<= 1) {
            int y = __shfl_up_sync(0xffffffffu, w, off);
            if (tid >= off) w += y;
        }
        wsum[tid] = w;
    }
    __syncthreads();
    int incl = x + ((tid >= 32) ? wsum[(tid >> 5) - 1] : 0);
    if (idx < NN) g_off[idx] = incl - v;
    if (tid == 1023) g_bsum[b] = incl;
}

__global__ void k_scan2() {
    int tid = threadIdx.x;
    __shared__ int ws[2];
    int v = (tid < NBLK) ? g_bsum[tid] : 0;
    int x = v;
    #pragma unroll
    for (int off = 1; off < 32; off <<= 1) {
        int y = __shfl_up_sync(0xffffffffu, x, off);
        if ((tid & 31) >= off) x += y;
    }
    if ((tid & 31) == 31) ws[tid >> 5] = x;
    __syncthreads();
    int incl = x + ((tid >= 32) ? ws[0] : 0);
    if (tid < NBLK) g_bpre[tid] = incl - v;
    if (tid == NBLK - 1) g_off[NN] = incl;
}

__global__ void k_scan3() {
    int idx = blockIdx.x * 1024 + threadIdx.x;
    if (idx < NN) g_off[idx] += g_bpre[blockIdx.x];
}

__global__ void k_fill(const int* __restrict__ ei) {
    int e = blockIdx.x * blockDim.x + threadIdx.x;
    if (e >= ETOT) return;
    int src, dst;
    if (e < EIN) { src = ei[e]; dst = ei[EIN + e]; }
    else         { src = e - EIN; dst = e - EIN; }
    int pos = g_off[dst] + atomicAdd(&g_fill[dst], 1);
    g_src[pos] = src;
}

// ---------------- fp16 HMMA GEMM (3-stage cp.async) + attn epilogue ---------
#define SMSH   40
#define STAGEH (128 * SMSH)

__device__ __forceinline__ void cpa16(uint32_t dst, const void* src, bool p) {
    int sz = p ? 16 : 0;
    asm volatile("cp.async.cg.shared.global [%0], [%1], 16, %2;"
                 :: "r"(dst), "l"(src), "r"(sz));
}

__global__ __launch_bounds__(256, 2)
void k_gemm_tc(const __half* __restrict__ Ain, const __half* __restrict__ B,
               const float* __restrict__ as_, const float* __restrict__ ad_,
               int M, int N, int K, int C) {
    extern __shared__ char smraw[];
    __half* hsm = (__half*)smraw;
    const __half* A = Ain ? Ain : g_a16;

    const int tid  = threadIdx.x;
    const int lane = tid & 31;
    const int wid  = tid >> 5;
    const int gid  = lane >> 2;
    const int tg   = lane & 3;
    const int wm   = (wid >> 2) * 64;
    const int wn   = (wid & 3) * 32;

    const int bm = blockIdx.y * 128;
    const int bn = blockIdx.x * 128;

    const int r0 = tid >> 2;
    const int kq = (tid & 3) * 8;

    const int am0 = bm + r0, am1 = bm + r0 + 64;
    const bool p0 = am0 < M, p1 = am1 < M;
    const __half* arow0 = A + (size_t)(p0 ? am0 : 0) * K + kq;
    const __half* arow1 = A + (size_t)(p1 ? am1 : 0) * K + kq;
    const __half* brow0 = B + (size_t)(bn + r0) * K + kq;
    const __half* brow1 = B + (size_t)(bn + r0 + 64) * K + kq;

    uint32_t sm_base = (uint32_t)__cvta_generic_to_shared(hsm) + (r0 * SMSH + kq) * 2;
    const uint32_t stg   = STAGEH * 2;
    const uint32_t boff  = 3 * stg;
    const uint32_t half_ = 64 * SMSH * 2;

    float acc[4][4][4];
    #pragma unroll
    for (int mt = 0; mt < 4; mt++)
        #pragma unroll
        for (int nt = 0; nt < 4; nt++)
            #pragma unroll
            for (int i = 0; i < 4; i++) acc[mt][nt][i] = 0.f;

    const int KC = K >> 5;

    auto issue = [&](int kc) {
        int buf = kc % 3;
        int ko = kc * 32;
        cpa16(sm_base + buf * stg,                arow0 + ko, p0);
        cpa16(sm_base + buf * stg + half_,        arow1 + ko, p1);
        cpa16(sm_base + boff + buf * stg,         brow0 + ko, true);
        cpa16(sm_base + boff + buf * stg + half_, brow1 + ko, true);
        asm volatile("cp.async.commit_group;");
    };

    issue(0);
    issue(1);

    for (int kc = 0; kc < KC; kc++) {
        if (kc + 1 < KC) asm volatile("cp.async.wait_group 1;");
        else             asm volatile("cp.async.wait_group 0;");
        __syncthreads();
        if (kc + 2 < KC) issue(kc + 2);

        const __half* as = hsm + (kc % 3) * STAGEH;
        const __half* bs = hsm + 3 * STAGEH + (kc % 3) * STAGEH;
        #pragma unroll
        for (int s = 0; s < 2; s++) {
            int kl = s * 16;
            uint32_t af[4][4], bf[4][2];
            #pragma unroll
            for (int mt = 0; mt < 4; mt++) {
                int m = wm + mt * 16 + gid;
                af[mt][0] = *(const uint32_t*)&as[m * SMSH + kl + 2 * tg];
                af[mt][1] = *(const uint32_t*)&as[(m + 8) * SMSH + kl + 2 * tg];
                af[mt][2] = *(const uint32_t*)&as[m * SMSH + kl + 8 + 2 * tg];
                af[mt][3] = *(const uint32_t*)&as[(m + 8) * SMSH + kl + 8 + 2 * tg];
            }
            #pragma unroll
            for (int nt = 0; nt < 4; nt++) {
                int n = wn + nt * 8 + gid;
                bf[nt][0] = *(const uint32_t*)&bs[n * SMSH + kl + 2 * tg];
                bf[nt][1] = *(const uint32_t*)&bs[n * SMSH + kl + 8 + 2 * tg];
            }
            #pragma unroll
            for (int mt = 0; mt < 4; mt++)
                #pragma unroll
                for (int nt = 0; nt < 4; nt++) {
                    asm volatile(
                        "mma.sync.aligned.m16n8k16.row.col.f32.f16.f16.f32 "
                        "{%0,%1,%2,%3}, {%4,%5,%6,%7}, {%8,%9}, {%0,%1,%2,%3};"
                        : "+f"(acc[mt][nt][0]), "+f"(acc[mt][nt][1]),
                          "+f"(acc[mt][nt][2]), "+f"(acc[mt][nt][3])
                        : "r"(af[mt][0]), "r"(af[mt][1]), "r"(af[mt][2]), "r"(af[mt][3]),
                          "r"(bf[nt][0]), "r"(bf[nt][1]));
                }
        }
    }

    // ---- epilogue 1: store h as fp16 ----
    #pragma unroll
    for (int mt = 0; mt < 4; mt++) {
        int gm0 = bm + wm + mt * 16 + gid;
        int gm1 = gm0 + 8;
        #pragma unroll
        for (int nt = 0; nt < 4; nt++) {
            int gn = bn + wn + nt * 8 + tg * 2;
            if (gm0 < M)
                *(__half2*)(g_h16 + (size_t)gm0 * N + gn) =
                    __floats2half2_rn(acc[mt][nt][0], acc[mt][nt][1]);
            if (gm1 < M)
                *(__half2*)(g_h16 + (size_t)gm1 * N + gn) =
                    __floats2half2_rn(acc[mt][nt][2], acc[mt][nt][3]);
        }
    }

    // ---- epilogue 2: es/ed via smem reduction, direct store ----
    const int NH = 128 / C;
    float* red = (float*)smraw;
    __syncthreads();
    for (int i = tid; i < 128 * NH * 2; i += 256) red[i] = 0.f;
    __syncthreads();

    float av[4][2], dv[4][2];
    #pragma unroll
    for (int nt = 0; nt < 4; nt++) {
        int gc = bn + wn + nt * 8 + tg * 2;
        av[nt][0] = __ldg(as_ + gc);  av[nt][1] = __ldg(as_ + gc + 1);
        dv[nt][0] = __ldg(ad_ + gc);  dv[nt][1] = __ldg(ad_ + gc + 1);
    }
    const bool two = (C == 16);
    const int hl0 = wn / C;
    #pragma unroll
    for (int mt = 0; mt < 4; mt++) {
        #pragma unroll
        for (int hh = 0; hh < 2; hh++) {
            int rl = wm + mt * 16 + gid + hh * 8;
            float pes[2] = {0.f, 0.f}, ped[2] = {0.f, 0.f};
            #pragma unroll
            for (int nt = 0; nt < 4; nt++) {
                int sp = two ? (nt >> 1) : 0;
                float a0 = acc[mt][nt][hh * 2 + 0];
                float a1 = acc[mt][nt][hh * 2 + 1];
                pes[sp] += a0 * av[nt][0] + a1 * av[nt][1];
                ped[sp] += a0 * dv[nt][0] + a1 * dv[nt][1];
            }
            #pragma unroll
            for (int off = 1; off <= 2; off <<= 1) {
                pes[0] += __shfl_xor_sync(0xffffffffu, pes[0], off);
                ped[0] += __shfl_xor_sync(0xffffffffu, ped[0], off);
                pes[1] += __shfl_xor_sync(0xffffffffu, pes[1], off);
                ped[1] += __shfl_xor_sync(0xffffffffu, ped[1], off);
            }
            if (tg == 0) {
                atomicAdd(&red[rl * NH + hl0], pes[0]);
                atomicAdd(&red[128 * NH + rl * NH + hl0], ped[0]);
                if (two) {
                    atomicAdd(&red[rl * NH + hl0 + 1], pes[1]);
                    atomicAdd(&red[128 * NH + rl * NH + hl0 + 1], ped[1]);
                }
            }
        }
    }
    __syncthreads();
    const int hbase = bn / C;
    for (int i = tid; i < 128 * NH; i += 256) {
        int rl = i / NH, hl = i % NH;
        int row = bm + rl;
        if (row < M) {
            g_es[row * 8 + hbase + hl] = red[i];
            g_ed[row * 8 + hbase + hl] = red[128 * NH + i];
        }
    }
}

// ---------------- fused softmax + aggregation (LDG.128, layers 0,1,3) --------
template <int LOG2C, bool ELU, int LOG2S>
__global__ void k_agg4(const float* __restrict__ bias) {
    int gw = (blockIdx.x * blockDim.x + threadIdx.x) >> 5;
    int node = gw >> LOG2S;
    if (node >= NN) return;
    int part = gw & ((1 << LOG2S) - 1);
    const int lane = threadIdx.x & 31;
    const int Fout = 256 << LOG2S;
    const int base = part * 256;
    const int f = base + lane * 8;
    const int head = f >> LOG2C;
    const int ehead = lane & 7;
    const float edv = g_ed[node * 8 + ehead];
    int beg = g_off[node], end = g_off[node + 1];

    float acc[8];
    #pragma unroll
    for (int j = 0; j < 8; j++) acc[j] = 0.f;
    float sm = 0.f;

    int i = beg;
    for (; i + 4 <= end; i += 4) {
        int s0 = g_src[i],     s1 = g_src[i + 1];
        int s2 = g_src[i + 2], s3 = g_src[i + 3];
        int sel = lane >> 3;
        int ss = (sel == 0) ? s0 : (sel == 1) ? s1 : (sel == 2) ? s2 : s3;
        float e = __ldg(&g_es[ss * 8 + ehead]) + edv;
        e = e > 0.f ? e : 0.2f * e;
        float aw = __expf(e);
        sm += aw;
        uint4 u0 = __ldg((const uint4*)(g_h16 + (size_t)s0 * Fout + f));
        uint4 u1 = __ldg((const uint4*)(g_h16 + (size_t)s1 * Fout + f));
        uint4 u2 = __ldg((const uint4*)(g_h16 + (size_t)s2 * Fout + f));
        uint4 u3 = __ldg((const uint4*)(g_h16 + (size_t)s3 * Fout + f));
        float al0 = __shfl_sync(0xffffffffu, aw, head);
        float al1 = __shfl_sync(0xffffffffu, aw, 8 + head);
        float al2 = __shfl_sync(0xffffffffu, aw, 16 + head);
        float al3 = __shfl_sync(0xffffffffu, aw, 24 + head);
        const uint32_t* w0 = (const uint32_t*)&u0;
        const uint32_t* w1 = (const uint32_t*)&u1;
        const uint32_t* w2 = (const uint32_t*)&u2;
        const uint32_t* w3 = (const uint32_t*)&u3;
        #pragma unroll
        for (int q = 0; q < 4; q++) {
            float2 v0 = __half22float2(*(const __half2*)&w0[q]);
            float2 v1 = __half22float2(*(const __half2*)&w1[q]);
            float2 v2 = __half22float2(*(const __half2*)&w2[q]);
            float2 v3 = __half22float2(*(const __half2*)&w3[q]);
            acc[q*2+0] = fmaf(al0, v0.x, fmaf(al1, v1.x,
                          fmaf(al2, v2.x, fmaf(al3, v3.x, acc[q*2+0]))));
            acc[q*2+1] = fmaf(al0, v0.y, fmaf(al1, v1.y,
                          fmaf(al2, v2.y, fmaf(al3, v3.y, acc[q*2+1]))));
        }
    }
    for (; i < end; i++) {
        int s0 = g_src[i];
        float a0 = 0.f;
        if (lane < 8) {
            float e = __ldg(&g_es[s0 * 8 + ehead]) + edv;
            e = e > 0.f ? e : 0.2f * e;
            a0 = __expf(e);
        }
        sm += a0;
        float al0 = __shfl_sync(0xffffffffu, a0, head);
        uint4 u0 = __ldg((const uint4*)(g_h16 + (size_t)s0 * Fout + f));
        const uint32_t* w0 = (const uint32_t*)&u0;
        #pragma unroll
        for (int q = 0; q < 4; q++) {
            float2 v0 = __half22float2(*(const __half2*)&w0[q]);
            acc[q*2+0] = fmaf(al0, v0.x, acc[q*2+0]);
            acc[q*2+1] = fmaf(al0, v0.y, acc[q*2+1]);
        }
    }

    sm += __shfl_xor_sync(0xffffffffu, sm, 8);
    sm += __shfl_xor_sync(0xffffffffu, sm, 16);
    float inv = 1.f / __shfl_sync(0xffffffffu, sm, head);

    float4 b0 = __ldg((const float4*)(bias + f));
    float4 b1 = __ldg((const float4*)(bias + f + 4));
    float bb[8] = {b0.x, b0.y, b0.z, b0.w, b1.x, b1.y, b1.z, b1.w};
    uint4 o;
    uint32_t* ow = (uint32_t*)&o;
    #pragma unroll
    for (int q = 0; q < 4; q++) {
        float v0 = fmaf(acc[q*2+0], inv, bb[q*2+0]);
        float v1 = fmaf(acc[q*2+1], inv, bb[q*2+1]);
        if (ELU) {
            v0 = v0 > 0.f ? v0 : expm1f(v0);
            v1 = v1 > 0.f ? v1 : expm1f(v1);
        }
        __half2 h = __floats2half2_rn(v0, v1);
        ow[q] = *(uint32_t*)&h;
    }
    __stcs((uint4*)(g_a16 + (size_t)node * Fout + f), o);
}

// ---------------- fused softmax + aggregation (uint2, layer 2) ---------------
template <bool ELU>
__global__ void k_agg2(const float* __restrict__ bias) {
    int node = (blockIdx.x * blockDim.x + threadIdx.x) >> 5;
    if (node >= NN) return;
    const int lane = threadIdx.x & 31;
    const int Fout = 128;
    const int f = lane * 4;
    const int head = f >> 4;
    const int ehead = lane & 7;
    const float edv = g_ed[node * 8 + ehead];
    int beg = g_off[node], end = g_off[node + 1];

    float4 acc = make_float4(0.f, 0.f, 0.f, 0.f);
    float sm = 0.f;

    int i = beg;
    for (; i + 4 <= end; i += 4) {
        int s0 = g_src[i],     s1 = g_src[i + 1];
        int s2 = g_src[i + 2], s3 = g_src[i + 3];
        int sel = lane >> 3;
        int ss = (sel == 0) ? s0 : (sel == 1) ? s1 : (sel == 2) ? s2 : s3;
        float e = __ldg(&g_es[ss * 8 + ehead]) + edv;
        e = e > 0.f ? e : 0.2f * e;
        float aw = __expf(e);
        sm += aw;
        uint2 u0 = __ldg((const uint2*)(g_h16 + (size_t)s0 * Fout + f));
        uint2 u1 = __ldg((const uint2*)(g_h16 + (size_t)s1 * Fout + f));
        uint2 u2 = __ldg((const uint2*)(g_h16 + (size_t)s2 * Fout + f));
        uint2 u3 = __ldg((const uint2*)(g_h16 + (size_t)s3 * Fout + f));
        float al0 = __shfl_sync(0xffffffffu, aw, head);
        float al1 = __shfl_sync(0xffffffffu, aw, 8 + head);
        float al2 = __shfl_sync(0xffffffffu, aw, 16 + head);
        float al3 = __shfl_sync(0xffffffffu, aw, 24 + head);
        float2 lo0 = __half22float2(*(__half2*)&u0.x);
        float2 hi0 = __half22float2(*(__half2*)&u0.y);
        float2 lo1 = __half22float2(*(__half2*)&u1.x);
        float2 hi1 = __half22float2(*(__half2*)&u1.y);
        float2 lo2 = __half22float2(*(__half2*)&u2.x);
        float2 hi2 = __half22float2(*(__half2*)&u2.y);
        float2 lo3 = __half22float2(*(__half2*)&u3.x);
        float2 hi3 = __half22float2(*(__half2*)&u3.y);
        acc.x = fmaf(al0, lo0.x, fmaf(al1, lo1.x, fmaf(al2, lo2.x, fmaf(al3, lo3.x, acc.x))));
        acc.y = fmaf(al0, lo0.y, fmaf(al1, lo1.y, fmaf(al2, lo2.y, fmaf(al3, lo3.y, acc.y))));
        acc.z = fmaf(al0, hi0.x, fmaf(al1, hi1.x, fmaf(al2, hi2.x, fmaf(al3, hi3.x, acc.z))));
        acc.w = fmaf(al0, hi0.y, fmaf(al1, hi1.y, fmaf(al2, hi2.y, fmaf(al3, hi3.y, acc.w))));
    }
    for (; i < end; i++) {
        int s0 = g_src[i];
        float a0 = 0.f;
        if (lane < 8) {
            float e = __ldg(&g_es[s0 * 8 + ehead]) + edv;
            e = e > 0.f ? e : 0.2f * e;
            a0 = __expf(e);
        }
        sm += a0;
        float al0 = __shfl_sync(0xffffffffu, a0, head);
        uint2 u0 = __ldg((const uint2*)(g_h16 + (size_t)s0 * Fout + f));
        float2 lo0 = __half22float2(*(__half2*)&u0.x);
        float2 hi0 = __half22float2(*(__half2*)&u0.y);
        acc.x = fmaf(al0, lo0.x, acc.x);
        acc.y = fmaf(al0, lo0.y, acc.y);
        acc.z = fmaf(al0, hi0.x, acc.z);
        acc.w = fmaf(al0, hi0.y, acc.w);
    }

    sm += __shfl_xor_sync(0xffffffffu, sm, 8);
    sm += __shfl_xor_sync(0xffffffffu, sm, 16);
    float inv = 1.f / __shfl_sync(0xffffffffu, sm, head);

    float4 b4 = __ldg((const float4*)(bias + f));
    float v0 = fmaf(acc.x, inv, b4.x);
    float v1 = fmaf(acc.y, inv, b4.y);
    float v2 = fmaf(acc.z, inv, b4.z);
    float v3 = fmaf(acc.w, inv, b4.w);
    if (ELU) {
        v0 = v0 > 0.f ? v0 : expm1f(v0);
        v1 = v1 > 0.f ? v1 : expm1f(v1);
        v2 = v2 > 0.f ? v2 : expm1f(v2);
        v3 = v3 > 0.f ? v3 : expm1f(v3);
    }
    __half2 h01 = __floats2half2_rn(v0, v1);
    __half2 h23 = __floats2half2_rn(v2, v3);
    uint2 o;
    *(__half2*)&o.x = h01;
    *(__half2*)&o.y = h23;
    __stcs((uint2*)(g_a16 + (size_t)node * Fout + f), o);
}

// ---------------- pooling (init also clears CSR scratch) ---------------------
__global__ void k_pool_init() {
    int i = blockIdx.x * blockDim.x + threadIdx.x;
    if (i < GMAX * 512) g_pool[i] = 0.f;
    if (i < GMAX) g_cnt[i] = 0.f;
    if (i < NN) { g_deg[i] = 0; g_fill[i] = 0; }
}

__global__ void k_pool(const int* __restrict__ batch) {
    int f = threadIdx.x;
    int n0 = blockIdx.x * 512;
    int n1 = n0 + 512; if (n1 > NN) n1 = NN;
    if (n0 >= NN) return;
    float acc = 0.f;
    int cur = __ldg(&batch[n0]);
    float cnt = 0.f;
    for (int n = n0; n < n1; n++) {
        int b = __ldg(&batch[n]);
        if (b != cur) {
            atomicAdd(&g_pool[cur * 512 + f], acc);
            if (f == 0) atomicAdd(&g_cnt[cur], cnt);
            acc = 0.f; cnt = 0.f; cur = b;
        }
        acc += __half2float(g_a16[(size_t)n * 512 + f]);
        cnt += 1.f;
    }
    atomicAdd(&g_pool[cur * 512 + f], acc);
    if (f == 0) atomicAdd(&g_cnt[cur], cnt);
}

// ---------------- MLP head: warp-per-output, coalesced lw1 reads -------------
__global__ void k_mlp1(const float* __restrict__ lw1, const float* __restrict__ lb1) {
    int w = (blockIdx.x * blockDim.x + threadIdx.x) >> 5;   // 0..2047
    if (w >= GMAX * 32) return;
    int lane = threadIdx.x & 31;
    int g = w >> 5, j = w & 31;
    const float* pp = g_pool + g * 512;
    const float* wp = lw1 + j * 512;
    float s = 0.f;
    #pragma unroll 4
    for (int k = lane; k < 512; k += 32)
        s += pp[k] * __ldg(wp + k);
    #pragma unroll
    for (int off = 16; off; off >>= 1)
        s += __shfl_xor_sync(0xffffffffu, s, off);
    if (lane == 0) {
        float inv = 1.f / fmaxf(g_cnt[g], 1.f);
        s = s * inv + __ldg(lb1 + j);
        g_mlp[w] = s > 0.f ? s : expm1f(s);
    }
}

__global__ void k_mlp2(const float* __restrict__ lw2, const float* __restrict__ lb2,
                       float* __restrict__ out) {
    int t = threadIdx.x;
    if (t >= GMAX * 2) return;
    int g = t >> 1, o = t & 1;
    const float* mp = g_mlp + g * 32;
    const float* wp = lw2 + o * 32;
    float s = 0.f;
    #pragma unroll
    for (int k = 0; k < 32; k++) s += mp[k] * __ldg(wp + k);
    out[t] = s + __ldg(lb2 + o);
}

// ---------------- launch -----------------------------------------------------
#define GEMM_SMEM (6 * STAGEH * 2)   // 61440 bytes

extern "C" void kernel_launch(void* const* d_in, const int* in_sizes, int n_in,
                              void* d_out, int out_size) {
    const float* x     = (const float*)d_in[0];
    const int*   ei    = (const int*)  d_in[1];
    const int*   batch = (const int*)  d_in[2];
    const float *W[4], *as_[4], *ad_[4], *bb[4];
    for (int l = 0; l < 4; l++) {
        W[l]   = (const float*)d_in[3 + l * 4];
        as_[l] = (const float*)d_in[4 + l * 4];
        ad_[l] = (const float*)d_in[5 + l * 4];
        bb[l]  = (const float*)d_in[6 + l * 4];
    }
    const float* lw1 = (const float*)d_in[19];
    const float* lb1 = (const float*)d_in[20];
    const float* lw2 = (const float*)d_in[21];
    const float* lb2 = (const float*)d_in[22];
    float* out = (float*)d_out;

    cudaFuncSetAttribute(k_gemm_tc, cudaFuncAttributeMaxDynamicSharedMemorySize,
                         GEMM_SMEM);

    const int woff[4] = {0, 65536, 196608, 229376};
    __half* w16_base;
    cudaGetSymbolAddress((void**)&w16_base, g_w16);
    __half* x16_base;
    cudaGetSymbolAddress((void**)&x16_base, g_x16);

    const int Fo[4]  = {512, 256, 128, 512};
    const int Cc[4]  = {64, 32, 16, 64};
    const int Fin[4] = {128, 512, 256, 128};

    k_round_all<<<(X4 + W4T + 255) / 256, 256>>>(x, W[0], W[1], W[2], W[3]);
    k_count<<<(ETOT + 255) / 256, 256>>>(ei);
    {
        dim3 gg(Fo[0] / 128, (NN + 127) / 128);
        k_gemm_tc<<<gg, 256, GEMM_SMEM>>>(x16_base, w16_base + woff[0],
                                          as_[0], ad_[0], NN, Fo[0], Fin[0], Cc[0]);
    }
    k_scan1<<<NBLK, 1024>>>();
    k_scan2<<<1, 64>>>();
    k_scan3<<<NBLK, 1024>>>();
    k_fill<<<(ETOT + 255) / 256, 256>>>(ei);

    {
        int nb = (NN * 2 * 32 + 255) / 256;
        k_agg4<6, true, 1><<<nb, 256>>>(bb[0]);
    }

    for (int l = 1; l < 4; l++) {
        dim3 gg(Fo[l] / 128, (NN + 127) / 128);
        k_gemm_tc<<<gg, 256, GEMM_SMEM>>>(nullptr, w16_base + woff[l],
                                          as_[l], ad_[l], NN, Fo[l], Fin[l], Cc[l]);
        if (l == 1) {
            int nb = (NN * 32 + 255) / 256;
            k_agg4<5, true, 0><<<nb, 256>>>(bb[l]);
        } else if (l == 2) {
            int nb = (NN * 32 + 255) / 256;
            k_agg2<true><<<nb, 256>>>(bb[l]);
        } else {
            int nb = (NN * 2 * 32 + 255) / 256;
            k_agg4<6, false, 1><<<nb, 256>>>(bb[l]);
        }
    }

    k_pool_init<<<(NN + 255) / 256, 256>>>();
    k_pool<<<(NN + 511) / 512, 512>>>(batch);
    k_mlp1<<<(GMAX * 32 * 32 + 255) / 256, 256>>>(lw1, lb1);
    k_mlp2<<<1, 128>>>(lw2, lb2, out);
}

// round 16
// speedup vs baseline: 2.2164x; 1.3067x over previous
#include <cuda_runtime.h>
#include <cuda_fp16.h>
#include <math.h>
#include <stdint.h>

#define NN    50000
#define EIN   800000
#define ETOT  850000
#define GMAX  64
#define NBLK  ((NN + 1023) / 1024)

// ---------------- scratch (device globals; zero-initialized at load) -------
__device__ int    g_deg[NN];
__device__ int    g_off[NN + 1];
__device__ int    g_fill[NN];
__device__ int    g_src[ETOT];
__device__ int    g_bsum[64];
__device__ int    g_bpre[64];
__device__ float  g_es[NN * 8];
__device__ float  g_ed[NN * 8];
__device__ __align__(16) __half g_h16[NN * 512];   // GEMM output h (fp16)
__device__ __align__(16) __half g_a16[NN * 512];   // agg output (fp16)
__device__ __align__(16) __half g_x16[NN * 128];   // fp16 x
__device__ __align__(16) __half g_w16[294912];     // fp16 W1..W4
__device__ float  g_pool[GMAX * 512];
__device__ float  g_cnt[GMAX];
__device__ float  g_mlp[GMAX * 32];

// ---------------- operand conversion (x + W1..W4 -> fp16, one kernel) ------
#define X4   (NN * 128 / 4)
#define W4T  (294912 / 4)
__global__ void k_round_all(const float* __restrict__ x,
                            const float* __restrict__ w1, const float* __restrict__ w2,
                            const float* __restrict__ w3, const float* __restrict__ w4) {
    int i = blockIdx.x * blockDim.x + threadIdx.x;
    const float4* s;
    uint2* d;
    if (i < X4) {
        s = (const float4*)x + i;
        d = (uint2*)g_x16 + i;
    } else {
        int j = i - X4;
        if (j >= W4T) return;
        d = (uint2*)g_w16 + j;
        if      (j < 16384) s = (const float4*)w1 + j;
        else if (j < 49152) s = (const float4*)w2 + (j - 16384);
        else if (j < 57344) s = (const float4*)w3 + (j - 49152);
        else                s = (const float4*)w4 + (j - 57344);
    }
    float4 v = *s;
    __half2 h01 = __floats2half2_rn(v.x, v.y);
    __half2 h23 = __floats2half2_rn(v.z, v.w);
    uint2 o;
    *(__half2*)&o.x = h01;
    *(__half2*)&o.y = h23;
    *d = o;
}

// ---------------- CSR build (2 edges per thread, int2 loads) -----------------
__global__ void k_count(const int* __restrict__ ei) {
    int e2 = blockIdx.x * blockDim.x + threadIdx.x;   // pair index
    int e = e2 * 2;
    if (e >= ETOT) return;
    if (e < EIN) {
        int2 dd = *(const int2*)(ei + EIN + e);
        atomicAdd(&g_deg[dd.x], 1);
        atomicAdd(&g_deg[dd.y], 1);
    } else {
        atomicAdd(&g_deg[e - EIN], 1);
        atomicAdd(&g_deg[e + 1 - EIN], 1);
    }
}

__global__ void k_scan1() {
    __shared__ int wsum[32];
    int b = blockIdx.x, tid = threadIdx.x;
    int idx = b * 1024 + tid;
    int v = (idx < NN) ? g_deg[idx] : 0;
    int x = v;
    #pragma unroll
    for (int off = 1; off < 32; off <<= 1) {
        int y = __shfl_up_sync(0xffffffffu, x, off);
        if ((tid & 31) >= off) x += y;
    }
    if ((tid & 31) == 31) wsum[tid >> 5] = x;
    __syncthreads();
    if (tid < 32) {
        int w = wsum[tid];
        #pragma unroll
        for (int off = 1; off < 32; off <<= 1) {
            int y = __shfl_up_sync(0xffffffffu, w, off);
            if (tid >= off) w += y;
        }
        wsum[tid] = w;
    }
    __syncthreads();
    int incl = x + ((tid >= 32) ? wsum[(tid >> 5) - 1] : 0);
    if (idx < NN) g_off[idx] = incl - v;
    if (tid == 1023) g_bsum[b] = incl;
}

__global__ void k_scan2() {
    int tid = threadIdx.x;
    __shared__ int ws[2];
    int v = (tid < NBLK) ? g_bsum[tid] : 0;
    int x = v;
    #pragma unroll
    for (int off = 1; off < 32; off <<= 1) {
        int y = __shfl_up_sync(0xffffffffu, x, off);
        if ((tid & 31) >= off) x += y;
    }
    if ((tid & 31) == 31) ws[tid >> 5] = x;
    __syncthreads();
    int incl = x + ((tid >= 32) ? ws[0] : 0);
    if (tid < NBLK) g_bpre[tid] = incl - v;
    if (tid == NBLK - 1) g_off[NN] = incl;
}

__global__ void k_scan3() {
    int idx = blockIdx.x * 1024 + threadIdx.x;
    if (idx < NN) g_off[idx] += g_bpre[blockIdx.x];
}

__global__ void k_fill(const int* __restrict__ ei) {
    int e2 = blockIdx.x * blockDim.x + threadIdx.x;
    int e = e2 * 2;
    if (e >= ETOT) return;
    if (e < EIN) {
        int2 ss = *(const int2*)(ei + e);
        int2 dd = *(const int2*)(ei + EIN + e);
        int p0 = g_off[dd.x] + atomicAdd(&g_fill[dd.x], 1);
        g_src[p0] = ss.x;
        int p1 = g_off[dd.y] + atomicAdd(&g_fill[dd.y], 1);
        g_src[p1] = ss.y;
    } else {
        int n0 = e - EIN, n1 = e + 1 - EIN;
        int p0 = g_off[n0] + atomicAdd(&g_fill[n0], 1);
        g_src[p0] = n0;
        int p1 = g_off[n1] + atomicAdd(&g_fill[n1], 1);
        g_src[p1] = n1;
    }
}

// ---------------- fp16 HMMA GEMM (3-stage cp.async) + attn epilogue ---------
#define SMSH   40
#define STAGEH (128 * SMSH)

__device__ __forceinline__ void cpa16(uint32_t dst, const void* src, bool p) {
    int sz = p ? 16 : 0;
    asm volatile("cp.async.cg.shared.global [%0], [%1], 16, %2;"
                 :: "r"(dst), "l"(src), "r"(sz));
}

__global__ __launch_bounds__(256, 2)
void k_gemm_tc(const __half* __restrict__ Ain, const __half* __restrict__ B,
               const float* __restrict__ as_, const float* __restrict__ ad_,
               int M, int N, int K, int C) {
    extern __shared__ char smraw[];
    __half* hsm = (__half*)smraw;
    const __half* A = Ain ? Ain : g_a16;

    const int tid  = threadIdx.x;
    const int lane = tid & 31;
    const int wid  = tid >> 5;
    const int gid  = lane >> 2;
    const int tg   = lane & 3;
    const int wm   = (wid >> 2) * 64;
    const int wn   = (wid & 3) * 32;

    const int bm = blockIdx.y * 128;
    const int bn = blockIdx.x * 128;

    const int r0 = tid >> 2;
    const int kq = (tid & 3) * 8;

    const int am0 = bm + r0, am1 = bm + r0 + 64;
    const bool p0 = am0 < M, p1 = am1 < M;
    const __half* arow0 = A + (size_t)(p0 ? am0 : 0) * K + kq;
    const __half* arow1 = A + (size_t)(p1 ? am1 : 0) * K + kq;
    const __half* brow0 = B + (size_t)(bn + r0) * K + kq;
    const __half* brow1 = B + (size_t)(bn + r0 + 64) * K + kq;

    uint32_t sm_base = (uint32_t)__cvta_generic_to_shared(hsm) + (r0 * SMSH + kq) * 2;
    const uint32_t stg   = STAGEH * 2;
    const uint32_t boff  = 3 * stg;
    const uint32_t half_ = 64 * SMSH * 2;

    float acc[4][4][4];
    #pragma unroll
    for (int mt = 0; mt < 4; mt++)
        #pragma unroll
        for (int nt = 0; nt < 4; nt++)
            #pragma unroll
            for (int i = 0; i < 4; i++) acc[mt][nt][i] = 0.f;

    const int KC = K >> 5;

    auto issue = [&](int kc) {
        int buf = kc % 3;
        int ko = kc * 32;
        cpa16(sm_base + buf * stg,                arow0 + ko, p0);
        cpa16(sm_base + buf * stg + half_,        arow1 + ko, p1);
        cpa16(sm_base + boff + buf * stg,         brow0 + ko, true);
        cpa16(sm_base + boff + buf * stg + half_, brow1 + ko, true);
        asm volatile("cp.async.commit_group;");
    };

    issue(0);
    issue(1);

    for (int kc = 0; kc < KC; kc++) {
        if (kc + 1 < KC) asm volatile("cp.async.wait_group 1;");
        else             asm volatile("cp.async.wait_group 0;");
        __syncthreads();
        if (kc + 2 < KC) issue(kc + 2);

        const __half* as = hsm + (kc % 3) * STAGEH;
        const __half* bs = hsm + 3 * STAGEH + (kc % 3) * STAGEH;
        #pragma unroll
        for (int s = 0; s < 2; s++) {
            int kl = s * 16;
            uint32_t af[4][4], bf[4][2];
            #pragma unroll
            for (int mt = 0; mt < 4; mt++) {
                int m = wm + mt * 16 + gid;
                af[mt][0] = *(const uint32_t*)&as[m * SMSH + kl + 2 * tg];
                af[mt][1] = *(const uint32_t*)&as[(m + 8) * SMSH + kl + 2 * tg];
                af[mt][2] = *(const uint32_t*)&as[m * SMSH + kl + 8 + 2 * tg];
                af[mt][3] = *(const uint32_t*)&as[(m + 8) * SMSH + kl + 8 + 2 * tg];
            }
            #pragma unroll
            for (int nt = 0; nt < 4; nt++) {
                int n = wn + nt * 8 + gid;
                bf[nt][0] = *(const uint32_t*)&bs[n * SMSH + kl + 2 * tg];
                bf[nt][1] = *(const uint32_t*)&bs[n * SMSH + kl + 8 + 2 * tg];
            }
            #pragma unroll
            for (int mt = 0; mt < 4; mt++)
                #pragma unroll
                for (int nt = 0; nt < 4; nt++) {
                    asm volatile(
                        "mma.sync.aligned.m16n8k16.row.col.f32.f16.f16.f32 "
                        "{%0,%1,%2,%3}, {%4,%5,%6,%7}, {%8,%9}, {%0,%1,%2,%3};"
                        : "+f"(acc[mt][nt][0]), "+f"(acc[mt][nt][1]),
                          "+f"(acc[mt][nt][2]), "+f"(acc[mt][nt][3])
                        : "r"(af[mt][0]), "r"(af[mt][1]), "r"(af[mt][2]), "r"(af[mt][3]),
                          "r"(bf[nt][0]), "r"(bf[nt][1]));
                }
        }
    }

    // ---- epilogue 1: store h as fp16 ----
    #pragma unroll
    for (int mt = 0; mt < 4; mt++) {
        int gm0 = bm + wm + mt * 16 + gid;
        int gm1 = gm0 + 8;
        #pragma unroll
        for (int nt = 0; nt < 4; nt++) {
            int gn = bn + wn + nt * 8 + tg * 2;
            if (gm0 < M)
                *(__half2*)(g_h16 + (size_t)gm0 * N + gn) =
                    __floats2half2_rn(acc[mt][nt][0], acc[mt][nt][1]);
            if (gm1 < M)
                *(__half2*)(g_h16 + (size_t)gm1 * N + gn) =
                    __floats2half2_rn(acc[mt][nt][2], acc[mt][nt][3]);
        }
    }

    // ---- epilogue 2: es/ed via smem reduction, direct store ----
    const int NH = 128 / C;
    float* red = (float*)smraw;
    __syncthreads();
    for (int i = tid; i < 128 * NH * 2; i += 256) red[i] = 0.f;
    __syncthreads();

    float av[4][2], dv[4][2];
    #pragma unroll
    for (int nt = 0; nt < 4; nt++) {
        int gc = bn + wn + nt * 8 + tg * 2;
        av[nt][0] = __ldg(as_ + gc);  av[nt][1] = __ldg(as_ + gc + 1);
        dv[nt][0] = __ldg(ad_ + gc);  dv[nt][1] = __ldg(ad_ + gc + 1);
    }
    const bool two = (C == 16);
    const int hl0 = wn / C;
    #pragma unroll
    for (int mt = 0; mt < 4; mt++) {
        #pragma unroll
        for (int hh = 0; hh < 2; hh++) {
            int rl = wm + mt * 16 + gid + hh * 8;
            float pes[2] = {0.f, 0.f}, ped[2] = {0.f, 0.f};
            #pragma unroll
            for (int nt = 0; nt < 4; nt++) {
                int sp = two ? (nt >> 1) : 0;
                float a0 = acc[mt][nt][hh * 2 + 0];
                float a1 = acc[mt][nt][hh * 2 + 1];
                pes[sp] += a0 * av[nt][0] + a1 * av[nt][1];
                ped[sp] += a0 * dv[nt][0] + a1 * dv[nt][1];
            }
            #pragma unroll
            for (int off = 1; off <= 2; off <<= 1) {
                pes[0] += __shfl_xor_sync(0xffffffffu, pes[0], off);
                ped[0] += __shfl_xor_sync(0xffffffffu, ped[0], off);
                pes[1] += __shfl_xor_sync(0xffffffffu, pes[1], off);
                ped[1] += __shfl_xor_sync(0xffffffffu, ped[1], off);
            }
            if (tg == 0) {
                atomicAdd(&red[rl * NH + hl0], pes[0]);
                atomicAdd(&red[128 * NH + rl * NH + hl0], ped[0]);
                if (two) {
                    atomicAdd(&red[rl * NH + hl0 + 1], pes[1]);
                    atomicAdd(&red[128 * NH + rl * NH + hl0 + 1], ped[1]);
                }
            }
        }
    }
    __syncthreads();
    const int hbase = bn / C;
    for (int i = tid; i < 128 * NH; i += 256) {
        int rl = i / NH, hl = i % NH;
        int row = bm + rl;
        if (row < M) {
            g_es[row * 8 + hbase + hl] = red[i];
            g_ed[row * 8 + hbase + hl] = red[128 * NH + i];
        }
    }
}

// ---------------- fused softmax + aggregation (LDG.128, layers 0,1,3) --------
template <int LOG2C, bool ELU, int LOG2S>
__global__ void k_agg4(const float* __restrict__ bias) {
    int gw = (blockIdx.x * blockDim.x + threadIdx.x) >> 5;
    int node = gw >> LOG2S;
    if (node >= NN) return;
    int part = gw & ((1 << LOG2S) - 1);
    const int lane = threadIdx.x & 31;
    const int Fout = 256 << LOG2S;
    const int base = part * 256;
    const int f = base + lane * 8;
    const int head = f >> LOG2C;
    const int ehead = lane & 7;
    const float edv = g_ed[node * 8 + ehead];
    int beg = g_off[node], end = g_off[node + 1];

    float acc[8];
    #pragma unroll
    for (int j = 0; j < 8; j++) acc[j] = 0.f;
    float sm = 0.f;

    int i = beg;
    for (; i + 4 <= end; i += 4) {
        int s0 = g_src[i],     s1 = g_src[i + 1];
        int s2 = g_src[i + 2], s3 = g_src[i + 3];
        int sel = lane >> 3;
        int ss = (sel == 0) ? s0 : (sel == 1) ? s1 : (sel == 2) ? s2 : s3;
        float e = __ldg(&g_es[ss * 8 + ehead]) + edv;
        e = e > 0.f ? e : 0.2f * e;
        float aw = __expf(e);
        sm += aw;
        uint4 u0 = __ldg((const uint4*)(g_h16 + (size_t)s0 * Fout + f));
        uint4 u1 = __ldg((const uint4*)(g_h16 + (size_t)s1 * Fout + f));
        uint4 u2 = __ldg((const uint4*)(g_h16 + (size_t)s2 * Fout + f));
        uint4 u3 = __ldg((const uint4*)(g_h16 + (size_t)s3 * Fout + f));
        float al0 = __shfl_sync(0xffffffffu, aw, head);
        float al1 = __shfl_sync(0xffffffffu, aw, 8 + head);
        float al2 = __shfl_sync(0xffffffffu, aw, 16 + head);
        float al3 = __shfl_sync(0xffffffffu, aw, 24 + head);
        const uint32_t* w0 = (const uint32_t*)&u0;
        const uint32_t* w1 = (const uint32_t*)&u1;
        const uint32_t* w2 = (const uint32_t*)&u2;
        const uint32_t* w3 = (const uint32_t*)&u3;
        #pragma unroll
        for (int q = 0; q < 4; q++) {
            float2 v0 = __half22float2(*(const __half2*)&w0[q]);
            float2 v1 = __half22float2(*(const __half2*)&w1[q]);
            float2 v2 = __half22float2(*(const __half2*)&w2[q]);
            float2 v3 = __half22float2(*(const __half2*)&w3[q]);
            acc[q*2+0] = fmaf(al0, v0.x, fmaf(al1, v1.x,
                          fmaf(al2, v2.x, fmaf(al3, v3.x, acc[q*2+0]))));
            acc[q*2+1] = fmaf(al0, v0.y, fmaf(al1, v1.y,
                          fmaf(al2, v2.y, fmaf(al3, v3.y, acc[q*2+1]))));
        }
    }
    for (; i < end; i++) {
        int s0 = g_src[i];
        float a0 = 0.f;
        if (lane < 8) {
            float e = __ldg(&g_es[s0 * 8 + ehead]) + edv;
            e = e > 0.f ? e : 0.2f * e;
            a0 = __expf(e);
        }
        sm += a0;
        float al0 = __shfl_sync(0xffffffffu, a0, head);
        uint4 u0 = __ldg((const uint4*)(g_h16 + (size_t)s0 * Fout + f));
        const uint32_t* w0 = (const uint32_t*)&u0;
        #pragma unroll
        for (int q = 0; q < 4; q++) {
            float2 v0 = __half22float2(*(const __half2*)&w0[q]);
            acc[q*2+0] = fmaf(al0, v0.x, acc[q*2+0]);
            acc[q*2+1] = fmaf(al0, v0.y, acc[q*2+1]);
        }
    }

    sm += __shfl_xor_sync(0xffffffffu, sm, 8);
    sm += __shfl_xor_sync(0xffffffffu, sm, 16);
    float inv = 1.f / __shfl_sync(0xffffffffu, sm, head);

    float4 b0 = __ldg((const float4*)(bias + f));
    float4 b1 = __ldg((const float4*)(bias + f + 4));
    float bb[8] = {b0.x, b0.y, b0.z, b0.w, b1.x, b1.y, b1.z, b1.w};
    uint4 o;
    uint32_t* ow = (uint32_t*)&o;
    #pragma unroll
    for (int q = 0; q < 4; q++) {
        float v0 = fmaf(acc[q*2+0], inv, bb[q*2+0]);
        float v1 = fmaf(acc[q*2+1], inv, bb[q*2+1]);
        if (ELU) {
            v0 = v0 > 0.f ? v0 : expm1f(v0);
            v1 = v1 > 0.f ? v1 : expm1f(v1);
        }
        __half2 h = __floats2half2_rn(v0, v1);
        ow[q] = *(uint32_t*)&h;
    }
    __stcs((uint4*)(g_a16 + (size_t)node * Fout + f), o);
}

// ---------------- fused softmax + aggregation (uint2, layer 2) ---------------
template <bool ELU>
__global__ void k_agg2(const float* __restrict__ bias) {
    int node = (blockIdx.x * blockDim.x + threadIdx.x) >> 5;
    if (node >= NN) return;
    const int lane = threadIdx.x & 31;
    const int Fout = 128;
    const int f = lane * 4;
    const int head = f >> 4;
    const int ehead = lane & 7;
    const float edv = g_ed[node * 8 + ehead];
    int beg = g_off[node], end = g_off[node + 1];

    float4 acc = make_float4(0.f, 0.f, 0.f, 0.f);
    float sm = 0.f;

    int i = beg;
    for (; i + 4 <= end; i += 4) {
        int s0 = g_src[i],     s1 = g_src[i + 1];
        int s2 = g_src[i + 2], s3 = g_src[i + 3];
        int sel = lane >> 3;
        int ss = (sel == 0) ? s0 : (sel == 1) ? s1 : (sel == 2) ? s2 : s3;
        float e = __ldg(&g_es[ss * 8 + ehead]) + edv;
        e = e > 0.f ? e : 0.2f * e;
        float aw = __expf(e);
        sm += aw;
        uint2 u0 = __ldg((const uint2*)(g_h16 + (size_t)s0 * Fout + f));
        uint2 u1 = __ldg((const uint2*)(g_h16 + (size_t)s1 * Fout + f));
        uint2 u2 = __ldg((const uint2*)(g_h16 + (size_t)s2 * Fout + f));
        uint2 u3 = __ldg((const uint2*)(g_h16 + (size_t)s3 * Fout + f));
        float al0 = __shfl_sync(0xffffffffu, aw, head);
        float al1 = __shfl_sync(0xffffffffu, aw, 8 + head);
        float al2 = __shfl_sync(0xffffffffu, aw, 16 + head);
        float al3 = __shfl_sync(0xffffffffu, aw, 24 + head);
        float2 lo0 = __half22float2(*(__half2*)&u0.x);
        float2 hi0 = __half22float2(*(__half2*)&u0.y);
        float2 lo1 = __half22float2(*(__half2*)&u1.x);
        float2 hi1 = __half22float2(*(__half2*)&u1.y);
        float2 lo2 = __half22float2(*(__half2*)&u2.x);
        float2 hi2 = __half22float2(*(__half2*)&u2.y);
        float2 lo3 = __half22float2(*(__half2*)&u3.x);
        float2 hi3 = __half22float2(*(__half2*)&u3.y);
        acc.x = fmaf(al0, lo0.x, fmaf(al1, lo1.x, fmaf(al2, lo2.x, fmaf(al3, lo3.x, acc.x))));
        acc.y = fmaf(al0, lo0.y, fmaf(al1, lo1.y, fmaf(al2, lo2.y, fmaf(al3, lo3.y, acc.y))));
        acc.z = fmaf(al0, hi0.x, fmaf(al1, hi1.x, fmaf(al2, hi2.x, fmaf(al3, hi3.x, acc.z))));
        acc.w = fmaf(al0, hi0.y, fmaf(al1, hi1.y, fmaf(al2, hi2.y, fmaf(al3, hi3.y, acc.w))));
    }
    for (; i < end; i++) {
        int s0 = g_src[i];
        float a0 = 0.f;
        if (lane < 8) {
            float e = __ldg(&g_es[s0 * 8 + ehead]) + edv;
            e = e > 0.f ? e : 0.2f * e;
            a0 = __expf(e);
        }
        sm += a0;
        float al0 = __shfl_sync(0xffffffffu, a0, head);
        uint2 u0 = __ldg((const uint2*)(g_h16 + (size_t)s0 * Fout + f));
        float2 lo0 = __half22float2(*(__half2*)&u0.x);
        float2 hi0 = __half22float2(*(__half2*)&u0.y);
        acc.x = fmaf(al0, lo0.x, acc.x);
        acc.y = fmaf(al0, lo0.y, acc.y);
        acc.z = fmaf(al0, hi0.x, acc.z);
        acc.w = fmaf(al0, hi0.y, acc.w);
    }

    sm += __shfl_xor_sync(0xffffffffu, sm, 8);
    sm += __shfl_xor_sync(0xffffffffu, sm, 16);
    float inv = 1.f / __shfl_sync(0xffffffffu, sm, head);

    float4 b4 = __ldg((const float4*)(bias + f));
    float v0 = fmaf(acc.x, inv, b4.x);
    float v1 = fmaf(acc.y, inv, b4.y);
    float v2 = fmaf(acc.z, inv, b4.z);
    float v3 = fmaf(acc.w, inv, b4.w);
    if (ELU) {
        v0 = v0 > 0.f ? v0 : expm1f(v0);
        v1 = v1 > 0.f ? v1 : expm1f(v1);
        v2 = v2 > 0.f ? v2 : expm1f(v2);
        v3 = v3 > 0.f ? v3 : expm1f(v3);
    }
    __half2 h01 = __floats2half2_rn(v0, v1);
    __half2 h23 = __floats2half2_rn(v2, v3);
    uint2 o;
    *(__half2*)&o.x = h01;
    *(__half2*)&o.y = h23;
    __stcs((uint2*)(g_a16 + (size_t)node * Fout + f), o);
}

// ---------------- pooling (init also clears CSR scratch) ---------------------
__global__ void k_pool_init() {
    int i = blockIdx.x * blockDim.x + threadIdx.x;
    if (i < GMAX * 512) g_pool[i] = 0.f;
    if (i < GMAX) g_cnt[i] = 0.f;
    if (i < NN) { g_deg[i] = 0; g_fill[i] = 0; }
}

#define POOL_CHUNK 128
__global__ void k_pool(const int* __restrict__ batch) {
    int f = threadIdx.x;
    int n0 = blockIdx.x * POOL_CHUNK;
    int n1 = n0 + POOL_CHUNK; if (n1 > NN) n1 = NN;
    if (n0 >= NN) return;
    float acc = 0.f;
    int cur = __ldg(&batch[n0]);
    float cnt = 0.f;
    for (int n = n0; n < n1; n++) {
        int b = __ldg(&batch[n]);
        if (b != cur) {
            atomicAdd(&g_pool[cur * 512 + f], acc);
            if (f == 0) atomicAdd(&g_cnt[cur], cnt);
            acc = 0.f; cnt = 0.f; cur = b;
        }
        acc += __half2float(g_a16[(size_t)n * 512 + f]);
        cnt += 1.f;
    }
    atomicAdd(&g_pool[cur * 512 + f], acc);
    if (f == 0) atomicAdd(&g_cnt[cur], cnt);
}

// ---------------- MLP head: warp-per-output, coalesced lw1 reads -------------
__global__ void k_mlp1(const float* __restrict__ lw1, const float* __restrict__ lb1) {
    int w = (blockIdx.x * blockDim.x + threadIdx.x) >> 5;
    if (w >= GMAX * 32) return;
    int lane = threadIdx.x & 31;
    int g = w >> 5, j = w & 31;
    const float* pp = g_pool + g * 512;
    const float* wp = lw1 + j * 512;
    float s = 0.f;
    #pragma unroll 4
    for (int k = lane; k < 512; k += 32)
        s += pp[k] * __ldg(wp + k);
    #pragma unroll
    for (int off = 16; off; off >>= 1)
        s += __shfl_xor_sync(0xffffffffu, s, off);
    if (lane == 0) {
        float inv = 1.f / fmaxf(g_cnt[g], 1.f);
        s = s * inv + __ldg(lb1 + j);
        g_mlp[w] = s > 0.f ? s : expm1f(s);
    }
}

__global__ void k_mlp2(const float* __restrict__ lw2, const float* __restrict__ lb2,
                       float* __restrict__ out) {
    int t = threadIdx.x;
    if (t >= GMAX * 2) return;
    int g = t >> 1, o = t & 1;
    const float* mp = g_mlp + g * 32;
    const float* wp = lw2 + o * 32;
    float s = 0.f;
    #pragma unroll
    for (int k = 0; k < 32; k++) s += mp[k] * __ldg(wp + k);
    out[t] = s + __ldg(lb2 + o);
}

// ---------------- launch -----------------------------------------------------
#define GEMM_SMEM (6 * STAGEH * 2)   // 61440 bytes

extern "C" void kernel_launch(void* const* d_in, const int* in_sizes, int n_in,
                              void* d_out, int out_size) {
    const float* x     = (const float*)d_in[0];
    const int*   ei    = (const int*)  d_in[1];
    const int*   batch = (const int*)  d_in[2];
    const float *W[4], *as_[4], *ad_[4], *bb[4];
    for (int l = 0; l < 4; l++) {
        W[l]   = (const float*)d_in[3 + l * 4];
        as_[l] = (const float*)d_in[4 + l * 4];
        ad_[l] = (const float*)d_in[5 + l * 4];
        bb[l]  = (const float*)d_in[6 + l * 4];
    }
    const float* lw1 = (const float*)d_in[19];
    const float* lb1 = (const float*)d_in[20];
    const float* lw2 = (const float*)d_in[21];
    const float* lb2 = (const float*)d_in[22];
    float* out = (float*)d_out;

    cudaFuncSetAttribute(k_gemm_tc, cudaFuncAttributeMaxDynamicSharedMemorySize,
                         GEMM_SMEM);

    const int woff[4] = {0, 65536, 196608, 229376};
    __half* w16_base;
    cudaGetSymbolAddress((void**)&w16_base, g_w16);
    __half* x16_base;
    cudaGetSymbolAddress((void**)&x16_base, g_x16);

    const int Fo[4]  = {512, 256, 128, 512};
    const int Cc[4]  = {64, 32, 16, 64};
    const int Fin[4] = {128, 512, 256, 128};

    k_round_all<<<(X4 + W4T + 255) / 256, 256>>>(x, W[0], W[1], W[2], W[3]);
    k_count<<<(ETOT / 2 + 255) / 256, 256>>>(ei);
    {
        dim3 gg(Fo[0] / 128, (NN + 127) / 128);
        k_gemm_tc<<<gg, 256, GEMM_SMEM>>>(x16_base, w16_base + woff[0],
                                          as_[0], ad_[0], NN, Fo[0], Fin[0], Cc[0]);
    }
    k_scan1<<<NBLK, 1024>>>();
    k_scan2<<<1, 64>>>();
    k_scan3<<<NBLK, 1024>>>();
    k_fill<<<(ETOT / 2 + 255) / 256, 256>>>(ei);

    {
        int nb = (NN * 2 * 32 + 255) / 256;
        k_agg4<6, true, 1><<<nb, 256>>>(bb[0]);
    }

    for (int l = 1; l < 4; l++) {
        dim3 gg(Fo[l] / 128, (NN + 127) / 128);
        k_gemm_tc<<<gg, 256, GEMM_SMEM>>>(nullptr, w16_base + woff[l],
                                          as_[l], ad_[l], NN, Fo[l], Fin[l], Cc[l]);
        if (l == 1) {
            int nb = (NN * 32 + 255) / 256;
            k_agg4<5, true, 0><<<nb, 256>>>(bb[l]);
        } else if (l == 2) {
            int nb = (NN * 32 + 255) / 256;
            k_agg2<true><<<nb, 256>>>(bb[l]);
        } else {
            int nb = (NN * 2 * 32 + 255) / 256;
            k_agg4<6, false, 1><<<nb, 256>>>(bb[l]);
        }
    }

    k_pool_init<<<(NN + 255) / 256, 256>>>();
    k_pool<<<(NN + POOL_CHUNK - 1) / POOL_CHUNK, 512>>>(batch);
    k_mlp1<<<(GMAX * 32 * 32 + 255) / 256, 256>>>(lw1, lb1);
    k_mlp2<<<1, 128>>>(lw2, lb2, out);
}

// round 17
// speedup vs baseline: 2.2454x; 1.0131x over previous
#include <cuda_runtime.h>
#include <cuda_fp16.h>
#include <math.h>
#include <stdint.h>

#define NN    50000
#define EIN   800000
#define ETOT  850000
#define GMAX  64
#define NBLK  ((NN + 1023) / 1024)

// ---------------- scratch (device globals; zero-initialized at load) -------
__device__ int    g_deg[NN];
__device__ int    g_off[NN + 1];
__device__ int    g_fill[NN];
__device__ int    g_src[ETOT];
__device__ int    g_bsum[64];
__device__ int    g_bpre[64];
__device__ float  g_es[NN * 8];
__device__ float  g_ed[NN * 8];
__device__ __align__(16) __half g_h16[NN * 512];   // GEMM output h (fp16)
__device__ __align__(16) __half g_a16[NN * 512];   // agg output (fp16)
__device__ __align__(16) __half g_x16[NN * 128];   // fp16 x
__device__ __align__(16) __half g_w16[294912];     // fp16 W1..W4
__device__ float  g_pool[GMAX * 512];
__device__ float  g_cnt[GMAX];
__device__ float  g_mlp[GMAX * 32];

// ---------------- operand conversion (x + W1..W4 -> fp16, one kernel) ------
#define X4   (NN * 128 / 4)
#define W4T  (294912 / 4)
__global__ void k_round_all(const float* __restrict__ x,
                            const float* __restrict__ w1, const float* __restrict__ w2,
                            const float* __restrict__ w3, const float* __restrict__ w4) {
    int i = blockIdx.x * blockDim.x + threadIdx.x;
    const float4* s;
    uint2* d;
    if (i < X4) {
        s = (const float4*)x + i;
        d = (uint2*)g_x16 + i;
    } else {
        int j = i - X4;
        if (j >= W4T) return;
        d = (uint2*)g_w16 + j;
        if      (j < 16384) s = (const float4*)w1 + j;
        else if (j < 49152) s = (const float4*)w2 + (j - 16384);
        else if (j < 57344) s = (const float4*)w3 + (j - 49152);
        else                s = (const float4*)w4 + (j - 57344);
    }
    float4 v = *s;
    __half2 h01 = __floats2half2_rn(v.x, v.y);
    __half2 h23 = __floats2half2_rn(v.z, v.w);
    uint2 o;
    *(__half2*)&o.x = h01;
    *(__half2*)&o.y = h23;
    *d = o;
}

// ---------------- CSR build (2 edges per thread, int2 loads) -----------------
__global__ void k_count(const int* __restrict__ ei) {
    int e2 = blockIdx.x * blockDim.x + threadIdx.x;
    int e = e2 * 2;
    if (e >= ETOT) return;
    if (e < EIN) {
        int2 dd = *(const int2*)(ei + EIN + e);
        atomicAdd(&g_deg[dd.x], 1);
        atomicAdd(&g_deg[dd.y], 1);
    } else {
        atomicAdd(&g_deg[e - EIN], 1);
        atomicAdd(&g_deg[e + 1 - EIN], 1);
    }
}

__global__ void k_scan1() {
    __shared__ int wsum[32];
    int b = blockIdx.x, tid = threadIdx.x;
    int idx = b * 1024 + tid;
    int v = (idx < NN) ? g_deg[idx] : 0;
    int x = v;
    #pragma unroll
    for (int off = 1; off < 32; off <<= 1) {
        int y = __shfl_up_sync(0xffffffffu, x, off);
        if ((tid & 31) >= off) x += y;
    }
    if ((tid & 31) == 31) wsum[tid >> 5] = x;
    __syncthreads();
    if (tid < 32) {
        int w = wsum[tid];
        #pragma unroll
        for (int off = 1; off < 32; off <<= 1) {
            int y = __shfl_up_sync(0xffffffffu, w, off);
            if (tid >= off) w += y;
        }
        wsum[tid] = w;
    }
    __syncthreads();
    int incl = x + ((tid >= 32) ? wsum[(tid >> 5) - 1] : 0);
    if (idx < NN) g_off[idx] = incl - v;
    if (tid == 1023) g_bsum[b] = incl;
}

__global__ void k_scan2() {
    int tid = threadIdx.x;
    __shared__ int ws[2];
    int v = (tid < NBLK) ? g_bsum[tid] : 0;
    int x = v;
    #pragma unroll
    for (int off = 1; off < 32; off <<= 1) {
        int y = __shfl_up_sync(0xffffffffu, x, off);
        if ((tid & 31) >= off) x += y;
    }
    if ((tid & 31) == 31) ws[tid >> 5] = x;
    __syncthreads();
    int incl = x + ((tid >= 32) ? ws[0] : 0);
    if (tid < NBLK) g_bpre[tid] = incl - v;
    if (tid == NBLK - 1) g_off[NN] = incl;
}

__global__ void k_scan3() {
    int idx = blockIdx.x * 1024 + threadIdx.x;
    if (idx < NN) g_off[idx] += g_bpre[blockIdx.x];
}

__global__ void k_fill(const int* __restrict__ ei) {
    int e2 = blockIdx.x * blockDim.x + threadIdx.x;
    int e = e2 * 2;
    if (e >= ETOT) return;
    if (e < EIN) {
        int2 ss = *(const int2*)(ei + e);
        int2 dd = *(const int2*)(ei + EIN + e);
        int p0 = g_off[dd.x] + atomicAdd(&g_fill[dd.x], 1);
        g_src[p0] = ss.x;
        int p1 = g_off[dd.y] + atomicAdd(&g_fill[dd.y], 1);
        g_src[p1] = ss.y;
    } else {
        int n0 = e - EIN, n1 = e + 1 - EIN;
        int p0 = g_off[n0] + atomicAdd(&g_fill[n0], 1);
        g_src[p0] = n0;
        int p1 = g_off[n1] + atomicAdd(&g_fill[n1], 1);
        g_src[p1] = n1;
    }
}

// ---------------- fp16 HMMA GEMM (3-stage cp.async, ldmatrix frags) ----------
#define SMSH   40
#define STAGEH (128 * SMSH)

__device__ __forceinline__ void cpa16(uint32_t dst, const void* src, bool p) {
    int sz = p ? 16 : 0;
    asm volatile("cp.async.cg.shared.global [%0], [%1], 16, %2;"
                 :: "r"(dst), "l"(src), "r"(sz));
}

__device__ __forceinline__ void ldsm_x4(uint32_t addr, uint32_t& r0, uint32_t& r1,
                                        uint32_t& r2, uint32_t& r3) {
    asm volatile("ldmatrix.sync.aligned.m8n8.x4.shared.b16 {%0,%1,%2,%3}, [%4];"
                 : "=r"(r0), "=r"(r1), "=r"(r2), "=r"(r3) : "r"(addr));
}

__device__ __forceinline__ void ldsm_x2(uint32_t addr, uint32_t& r0, uint32_t& r1) {
    asm volatile("ldmatrix.sync.aligned.m8n8.x2.shared.b16 {%0,%1}, [%2];"
                 : "=r"(r0), "=r"(r1) : "r"(addr));
}

__global__ __launch_bounds__(256, 2)
void k_gemm_tc(const __half* __restrict__ Ain, const __half* __restrict__ B,
               const float* __restrict__ as_, const float* __restrict__ ad_,
               int M, int N, int K, int C) {
    extern __shared__ char smraw[];
    __half* hsm = (__half*)smraw;
    const __half* A = Ain ? Ain : g_a16;

    const int tid  = threadIdx.x;
    const int lane = tid & 31;
    const int wid  = tid >> 5;
    const int gid  = lane >> 2;
    const int tg   = lane & 3;
    const int wm   = (wid >> 2) * 64;
    const int wn   = (wid & 3) * 32;

    const int bm = blockIdx.y * 128;
    const int bn = blockIdx.x * 128;

    const int r0 = tid >> 2;
    const int kq = (tid & 3) * 8;

    const int am0 = bm + r0, am1 = bm + r0 + 64;
    const bool p0 = am0 < M, p1 = am1 < M;
    const __half* arow0 = A + (size_t)(p0 ? am0 : 0) * K + kq;
    const __half* arow1 = A + (size_t)(p1 ? am1 : 0) * K + kq;
    const __half* brow0 = B + (size_t)(bn + r0) * K + kq;
    const __half* brow1 = B + (size_t)(bn + r0 + 64) * K + kq;

    uint32_t sm_u32  = (uint32_t)__cvta_generic_to_shared(hsm);
    uint32_t sm_base = sm_u32 + (r0 * SMSH + kq) * 2;
    const uint32_t stg   = STAGEH * 2;
    const uint32_t boff  = 3 * stg;
    const uint32_t half_ = 64 * SMSH * 2;

    // ldmatrix per-lane row/col (within tile)
    const int rowAl = wm + ((lane >> 3) & 1) * 8 + (lane & 7);
    const int colA  = (lane >> 4) * 8;
    const int rowBl = wn + (lane & 7);
    const int colB  = ((lane >> 3) & 1) * 8;

    float acc[4][4][4];
    #pragma unroll
    for (int mt = 0; mt < 4; mt++)
        #pragma unroll
        for (int nt = 0; nt < 4; nt++)
            #pragma unroll
            for (int i = 0; i < 4; i++) acc[mt][nt][i] = 0.f;

    const int KC = K >> 5;

    auto issue = [&](int kc) {
        int buf = kc % 3;
        int ko = kc * 32;
        cpa16(sm_base + buf * stg,                arow0 + ko, p0);
        cpa16(sm_base + buf * stg + half_,        arow1 + ko, p1);
        cpa16(sm_base + boff + buf * stg,         brow0 + ko, true);
        cpa16(sm_base + boff + buf * stg + half_, brow1 + ko, true);
        asm volatile("cp.async.commit_group;");
    };

    issue(0);
    issue(1);

    for (int kc = 0; kc < KC; kc++) {
        if (kc + 1 < KC) asm volatile("cp.async.wait_group 1;");
        else             asm volatile("cp.async.wait_group 0;");
        __syncthreads();
        if (kc + 2 < KC) issue(kc + 2);

        uint32_t asb = sm_u32 + (kc % 3) * stg;
        uint32_t bsb = sm_u32 + boff + (kc % 3) * stg;
        #pragma unroll
        for (int s = 0; s < 2; s++) {
            int kl = s * 16;
            uint32_t af[4][4], bf[4][2];
            #pragma unroll
            for (int mt = 0; mt < 4; mt++) {
                uint32_t addr = asb + (((rowAl + mt * 16) * SMSH) + kl + colA) * 2;
                ldsm_x4(addr, af[mt][0], af[mt][1], af[mt][2], af[mt][3]);
            }
            #pragma unroll
            for (int nt = 0; nt < 4; nt++) {
                uint32_t addr = bsb + (((rowBl + nt * 8) * SMSH) + kl + colB) * 2;
                ldsm_x2(addr, bf[nt][0], bf[nt][1]);
            }
            #pragma unroll
            for (int mt = 0; mt < 4; mt++)
                #pragma unroll
                for (int nt = 0; nt < 4; nt++) {
                    asm volatile(
                        "mma.sync.aligned.m16n8k16.row.col.f32.f16.f16.f32 "
                        "{%0,%1,%2,%3}, {%4,%5,%6,%7}, {%8,%9}, {%0,%1,%2,%3};"
                        : "+f"(acc[mt][nt][0]), "+f"(acc[mt][nt][1]),
                          "+f"(acc[mt][nt][2]), "+f"(acc[mt][nt][3])
                        : "r"(af[mt][0]), "r"(af[mt][1]), "r"(af[mt][2]), "r"(af[mt][3]),
                          "r"(bf[nt][0]), "r"(bf[nt][1]));
                }
        }
    }

    // ---- epilogue 1: store h as fp16 ----
    #pragma unroll
    for (int mt = 0; mt < 4; mt++) {
        int gm0 = bm + wm + mt * 16 + gid;
        int gm1 = gm0 + 8;
        #pragma unroll
        for (int nt = 0; nt < 4; nt++) {
            int gn = bn + wn + nt * 8 + tg * 2;
            if (gm0 < M)
                *(__half2*)(g_h16 + (size_t)gm0 * N + gn) =
                    __floats2half2_rn(acc[mt][nt][0], acc[mt][nt][1]);
            if (gm1 < M)
                *(__half2*)(g_h16 + (size_t)gm1 * N + gn) =
                    __floats2half2_rn(acc[mt][nt][2], acc[mt][nt][3]);
        }
    }

    // ---- epilogue 2: es/ed via smem reduction, direct store ----
    const int NH = 128 / C;
    float* red = (float*)smraw;
    __syncthreads();
    for (int i = tid; i < 128 * NH * 2; i += 256) red[i] = 0.f;
    __syncthreads();

    float av[4][2], dv[4][2];
    #pragma unroll
    for (int nt = 0; nt < 4; nt++) {
        int gc = bn + wn + nt * 8 + tg * 2;
        av[nt][0] = __ldg(as_ + gc);  av[nt][1] = __ldg(as_ + gc + 1);
        dv[nt][0] = __ldg(ad_ + gc);  dv[nt][1] = __ldg(ad_ + gc + 1);
    }
    const bool two = (C == 16);
    const int hl0 = wn / C;
    #pragma unroll
    for (int mt = 0; mt < 4; mt++) {
        #pragma unroll
        for (int hh = 0; hh < 2; hh++) {
            int rl = wm + mt * 16 + gid + hh * 8;
            float pes[2] = {0.f, 0.f}, ped[2] = {0.f, 0.f};
            #pragma unroll
            for (int nt = 0; nt < 4; nt++) {
                int sp = two ? (nt >> 1) : 0;
                float a0 = acc[mt][nt][hh * 2 + 0];
                float a1 = acc[mt][nt][hh * 2 + 1];
                pes[sp] += a0 * av[nt][0] + a1 * av[nt][1];
                ped[sp] += a0 * dv[nt][0] + a1 * dv[nt][1];
            }
            #pragma unroll
            for (int off = 1; off <= 2; off <<= 1) {
                pes[0] += __shfl_xor_sync(0xffffffffu, pes[0], off);
                ped[0] += __shfl_xor_sync(0xffffffffu, ped[0], off);
                pes[1] += __shfl_xor_sync(0xffffffffu, pes[1], off);
                ped[1] += __shfl_xor_sync(0xffffffffu, ped[1], off);
            }
            if (tg == 0) {
                atomicAdd(&red[rl * NH + hl0], pes[0]);
                atomicAdd(&red[128 * NH + rl * NH + hl0], ped[0]);
                if (two) {
                    atomicAdd(&red[rl * NH + hl0 + 1], pes[1]);
                    atomicAdd(&red[128 * NH + rl * NH + hl0 + 1], ped[1]);
                }
            }
        }
    }
    __syncthreads();
    const int hbase = bn / C;
    for (int i = tid; i < 128 * NH; i += 256) {
        int rl = i / NH, hl = i % NH;
        int row = bm + rl;
        if (row < M) {
            g_es[row * 8 + hbase + hl] = red[i];
            g_ed[row * 8 + hbase + hl] = red[128 * NH + i];
        }
    }
}

// ---------------- fused softmax + aggregation (LDG.128, layers 0,1,3) --------
template <int LOG2C, bool ELU, int LOG2S>
__global__ void k_agg4(const float* __restrict__ bias) {
    int gw = (blockIdx.x * blockDim.x + threadIdx.x) >> 5;
    int node = gw >> LOG2S;
    if (node >= NN) return;
    int part = gw & ((1 << LOG2S) - 1);
    const int lane = threadIdx.x & 31;
    const int Fout = 256 << LOG2S;
    const int base = part * 256;
    const int f = base + lane * 8;
    const int head = f >> LOG2C;
    const int ehead = lane & 7;
    const float edv = g_ed[node * 8 + ehead];
    int beg = g_off[node], end = g_off[node + 1];

    float acc[8];
    #pragma unroll
    for (int j = 0; j < 8; j++) acc[j] = 0.f;
    float sm = 0.f;

    int i = beg;
    for (; i + 4 <= end; i += 4) {
        int s0 = g_src[i],     s1 = g_src[i + 1];
        int s2 = g_src[i + 2], s3 = g_src[i + 3];
        int sel = lane >> 3;
        int ss = (sel == 0) ? s0 : (sel == 1) ? s1 : (sel == 2) ? s2 : s3;
        float e = __ldg(&g_es[ss * 8 + ehead]) + edv;
        e = e > 0.f ? e : 0.2f * e;
        float aw = __expf(e);
        sm += aw;
        uint4 u0 = __ldg((const uint4*)(g_h16 + (size_t)s0 * Fout + f));
        uint4 u1 = __ldg((const uint4*)(g_h16 + (size_t)s1 * Fout + f));
        uint4 u2 = __ldg((const uint4*)(g_h16 + (size_t)s2 * Fout + f));
        uint4 u3 = __ldg((const uint4*)(g_h16 + (size_t)s3 * Fout + f));
        float al0 = __shfl_sync(0xffffffffu, aw, head);
        float al1 = __shfl_sync(0xffffffffu, aw, 8 + head);
        float al2 = __shfl_sync(0xffffffffu, aw, 16 + head);
        float al3 = __shfl_sync(0xffffffffu, aw, 24 + head);
        const uint32_t* w0 = (const uint32_t*)&u0;
        const uint32_t* w1 = (const uint32_t*)&u1;
        const uint32_t* w2 = (const uint32_t*)&u2;
        const uint32_t* w3 = (const uint32_t*)&u3;
        #pragma unroll
        for (int q = 0; q < 4; q++) {
            float2 v0 = __half22float2(*(const __half2*)&w0[q]);
            float2 v1 = __half22float2(*(const __half2*)&w1[q]);
            float2 v2 = __half22float2(*(const __half2*)&w2[q]);
            float2 v3 = __half22float2(*(const __half2*)&w3[q]);
            acc[q*2+0] = fmaf(al0, v0.x, fmaf(al1, v1.x,
                          fmaf(al2, v2.x, fmaf(al3, v3.x, acc[q*2+0]))));
            acc[q*2+1] = fmaf(al0, v0.y, fmaf(al1, v1.y,
                          fmaf(al2, v2.y, fmaf(al3, v3.y, acc[q*2+1]))));
        }
    }
    for (; i < end; i++) {
        int s0 = g_src[i];
        float a0 = 0.f;
        if (lane < 8) {
            float e = __ldg(&g_es[s0 * 8 + ehead]) + edv;
            e = e > 0.f ? e : 0.2f * e;
            a0 = __expf(e);
        }
        sm += a0;
        float al0 = __shfl_sync(0xffffffffu, a0, head);
        uint4 u0 = __ldg((const uint4*)(g_h16 + (size_t)s0 * Fout + f));
        const uint32_t* w0 = (const uint32_t*)&u0;
        #pragma unroll
        for (int q = 0; q < 4; q++) {
            float2 v0 = __half22float2(*(const __half2*)&w0[q]);
            acc[q*2+0] = fmaf(al0, v0.x, acc[q*2+0]);
            acc[q*2+1] = fmaf(al0, v0.y, acc[q*2+1]);
        }
    }

    sm += __shfl_xor_sync(0xffffffffu, sm, 8);
    sm += __shfl_xor_sync(0xffffffffu, sm, 16);
    float inv = 1.f / __shfl_sync(0xffffffffu, sm, head);

    float4 b0 = __ldg((const float4*)(bias + f));
    float4 b1 = __ldg((const float4*)(bias + f + 4));
    float bb[8] = {b0.x, b0.y, b0.z, b0.w, b1.x, b1.y, b1.z, b1.w};
    uint4 o;
    uint32_t* ow = (uint32_t*)&o;
    #pragma unroll
    for (int q = 0; q < 4; q++) {
        float v0 = fmaf(acc[q*2+0], inv, bb[q*2+0]);
        float v1 = fmaf(acc[q*2+1], inv, bb[q*2+1]);
        if (ELU) {
            v0 = v0 > 0.f ? v0 : expm1f(v0);
            v1 = v1 > 0.f ? v1 : expm1f(v1);
        }
        __half2 h = __floats2half2_rn(v0, v1);
        ow[q] = *(uint32_t*)&h;
    }
    __stcs((uint4*)(g_a16 + (size_t)node * Fout + f), o);
}

// ---------------- fused softmax + aggregation (uint2, layer 2) ---------------
template <bool ELU>
__global__ void k_agg2(const float* __restrict__ bias) {
    int node = (blockIdx.x * blockDim.x + threadIdx.x) >> 5;
    if (node >= NN) return;
    const int lane = threadIdx.x & 31;
    const int Fout = 128;
    const int f = lane * 4;
    const int head = f >> 4;
    const int ehead = lane & 7;
    const float edv = g_ed[node * 8 + ehead];
    int beg = g_off[node], end = g_off[node + 1];

    float4 acc = make_float4(0.f, 0.f, 0.f, 0.f);
    float sm = 0.f;

    int i = beg;
    for (; i + 4 <= end; i += 4) {
        int s0 = g_src[i],     s1 = g_src[i + 1];
        int s2 = g_src[i + 2], s3 = g_src[i + 3];
        int sel = lane >> 3;
        int ss = (sel == 0) ? s0 : (sel == 1) ? s1 : (sel == 2) ? s2 : s3;
        float e = __ldg(&g_es[ss * 8 + ehead]) + edv;
        e = e > 0.f ? e : 0.2f * e;
        float aw = __expf(e);
        sm += aw;
        uint2 u0 = __ldg((const uint2*)(g_h16 + (size_t)s0 * Fout + f));
        uint2 u1 = __ldg((const uint2*)(g_h16 + (size_t)s1 * Fout + f));
        uint2 u2 = __ldg((const uint2*)(g_h16 + (size_t)s2 * Fout + f));
        uint2 u3 = __ldg((const uint2*)(g_h16 + (size_t)s3 * Fout + f));
        float al0 = __shfl_sync(0xffffffffu, aw, head);
        float al1 = __shfl_sync(0xffffffffu, aw, 8 + head);
        float al2 = __shfl_sync(0xffffffffu, aw, 16 + head);
        float al3 = __shfl_sync(0xffffffffu, aw, 24 + head);
        float2 lo0 = __half22float2(*(__half2*)&u0.x);
        float2 hi0 = __half22float2(*(__half2*)&u0.y);
        float2 lo1 = __half22float2(*(__half2*)&u1.x);
        float2 hi1 = __half22float2(*(__half2*)&u1.y);
        float2 lo2 = __half22float2(*(__half2*)&u2.x);
        float2 hi2 = __half22float2(*(__half2*)&u2.y);
        float2 lo3 = __half22float2(*(__half2*)&u3.x);
        float2 hi3 = __half22float2(*(__half2*)&u3.y);
        acc.x = fmaf(al0, lo0.x, fmaf(al1, lo1.x, fmaf(al2, lo2.x, fmaf(al3, lo3.x, acc.x))));
        acc.y = fmaf(al0, lo0.y, fmaf(al1, lo1.y, fmaf(al2, lo2.y, fmaf(al3, lo3.y, acc.y))));
        acc.z = fmaf(al0, hi0.x, fmaf(al1, hi1.x, fmaf(al2, hi2.x, fmaf(al3, hi3.x, acc.z))));
        acc.w = fmaf(al0, hi0.y, fmaf(al1, hi1.y, fmaf(al2, hi2.y, fmaf(al3, hi3.y, acc.w))));
    }
    for (; i < end; i++) {
        int s0 = g_src[i];
        float a0 = 0.f;
        if (lane < 8) {
            float e = __ldg(&g_es[s0 * 8 + ehead]) + edv;
            e = e > 0.f ? e : 0.2f * e;
            a0 = __expf(e);
        }
        sm += a0;
        float al0 = __shfl_sync(0xffffffffu, a0, head);
        uint2 u0 = __ldg((const uint2*)(g_h16 + (size_t)s0 * Fout + f));
        float2 lo0 = __half22float2(*(__half2*)&u0.x);
        float2 hi0 = __half22float2(*(__half2*)&u0.y);
        acc.x = fmaf(al0, lo0.x, acc.x);
        acc.y = fmaf(al0, lo0.y, acc.y);
        acc.z = fmaf(al0, hi0.x, acc.z);
        acc.w = fmaf(al0, hi0.y, acc.w);
    }

    sm += __shfl_xor_sync(0xffffffffu, sm, 8);
    sm += __shfl_xor_sync(0xffffffffu, sm, 16);
    float inv = 1.f / __shfl_sync(0xffffffffu, sm, head);

    float4 b4 = __ldg((const float4*)(bias + f));
    float v0 = fmaf(acc.x, inv, b4.x);
    float v1 = fmaf(acc.y, inv, b4.y);
    float v2 = fmaf(acc.z, inv, b4.z);
    float v3 = fmaf(acc.w, inv, b4.w);
    if (ELU) {
        v0 = v0 > 0.f ? v0 : expm1f(v0);
        v1 = v1 > 0.f ? v1 : expm1f(v1);
        v2 = v2 > 0.f ? v2 : expm1f(v2);
        v3 = v3 > 0.f ? v3 : expm1f(v3);
    }
    __half2 h01 = __floats2half2_rn(v0, v1);
    __half2 h23 = __floats2half2_rn(v2, v3);
    uint2 o;
    *(__half2*)&o.x = h01;
    *(__half2*)&o.y = h23;
    __stcs((uint2*)(g_a16 + (size_t)node * Fout + f), o);
}

// ---------------- pooling (init also clears CSR scratch) ---------------------
__global__ void k_pool_init() {
    int i = blockIdx.x * blockDim.x + threadIdx.x;
    if (i < GMAX * 512) g_pool[i] = 0.f;
    if (i < GMAX) g_cnt[i] = 0.f;
    if (i < NN) { g_deg[i] = 0; g_fill[i] = 0; }
}

#define POOL_CHUNK 128
__global__ void k_pool(const int* __restrict__ batch) {
    int f = threadIdx.x;
    int n0 = blockIdx.x * POOL_CHUNK;
    int n1 = n0 + POOL_CHUNK; if (n1 > NN) n1 = NN;
    if (n0 >= NN) return;
    float acc = 0.f;
    int cur = __ldg(&batch[n0]);
    float cnt = 0.f;
    for (int n = n0; n < n1; n++) {
        int b = __ldg(&batch[n]);
        if (b != cur) {
            atomicAdd(&g_pool[cur * 512 + f], acc);
            if (f == 0) atomicAdd(&g_cnt[cur], cnt);
            acc = 0.f; cnt = 0.f; cur = b;
        }
        acc += __half2float(g_a16[(size_t)n * 512 + f]);
        cnt += 1.f;
    }
    atomicAdd(&g_pool[cur * 512 + f], acc);
    if (f == 0) atomicAdd(&g_cnt[cur], cnt);
}

// ---------------- MLP head: warp-per-output, coalesced lw1 reads -------------
__global__ void k_mlp1(const float* __restrict__ lw1, const float* __restrict__ lb1) {
    int w = (blockIdx.x * blockDim.x + threadIdx.x) >> 5;
    if (w >= GMAX * 32) return;
    int lane = threadIdx.x & 31;
    int g = w >> 5, j = w & 31;
    const float* pp = g_pool + g * 512;
    const float* wp = lw1 + j * 512;
    float s = 0.f;
    #pragma unroll 4
    for (int k = lane; k < 512; k += 32)
        s += pp[k] * __ldg(wp + k);
    #pragma unroll
    for (int off = 16; off; off >>= 1)
        s += __shfl_xor_sync(0xffffffffu, s, off);
    if (lane == 0) {
        float inv = 1.f / fmaxf(g_cnt[g], 1.f);
        s = s * inv + __ldg(lb1 + j);
        g_mlp[w] = s > 0.f ? s : expm1f(s);
    }
}

__global__ void k_mlp2(const float* __restrict__ lw2, const float* __restrict__ lb2,
                       float* __restrict__ out) {
    int t = threadIdx.x;
    if (t >= GMAX * 2) return;
    int g = t >> 1, o = t & 1;
    const float* mp = g_mlp + g * 32;
    const float* wp = lw2 + o * 32;
    float s = 0.f;
    #pragma unroll
    for (int k = 0; k < 32; k++) s += mp[k] * __ldg(wp + k);
    out[t] = s + __ldg(lb2 + o);
}

// ---------------- launch -----------------------------------------------------
#define GEMM_SMEM (6 * STAGEH * 2)   // 61440 bytes

extern "C" void kernel_launch(void* const* d_in, const int* in_sizes, int n_in,
                              void* d_out, int out_size) {
    const float* x     = (const float*)d_in[0];
    const int*   ei    = (const int*)  d_in[1];
    const int*   batch = (const int*)  d_in[2];
    const float *W[4], *as_[4], *ad_[4], *bb[4];
    for (int l = 0; l < 4; l++) {
        W[l]   = (const float*)d_in[3 + l * 4];
        as_[l] = (const float*)d_in[4 + l * 4];
        ad_[l] = (const float*)d_in[5 + l * 4];
        bb[l]  = (const float*)d_in[6 + l * 4];
    }
    const float* lw1 = (const float*)d_in[19];
    const float* lb1 = (const float*)d_in[20];
    const float* lw2 = (const float*)d_in[21];
    const float* lb2 = (const float*)d_in[22];
    float* out = (float*)d_out;

    cudaFuncSetAttribute(k_gemm_tc, cudaFuncAttributeMaxDynamicSharedMemorySize,
                         GEMM_SMEM);

    const int woff[4] = {0, 65536, 196608, 229376};
    __half* w16_base;
    cudaGetSymbolAddress((void**)&w16_base, g_w16);
    __half* x16_base;
    cudaGetSymbolAddress((void**)&x16_base, g_x16);

    const int Fo[4]  = {512, 256, 128, 512};
    const int Cc[4]  = {64, 32, 16, 64};
    const int Fin[4] = {128, 512, 256, 128};

    k_round_all<<<(X4 + W4T + 255) / 256, 256>>>(x, W[0], W[1], W[2], W[3]);
    k_count<<<(ETOT / 2 + 255) / 256, 256>>>(ei);
    {
        dim3 gg(Fo[0] / 128, (NN + 127) / 128);
        k_gemm_tc<<<gg, 256, GEMM_SMEM>>>(x16_base, w16_base + woff[0],
                                          as_[0], ad_[0], NN, Fo[0], Fin[0], Cc[0]);
    }
    k_scan1<<<NBLK, 1024>>>();
    k_scan2<<<1, 64>>>();
    k_scan3<<<NBLK, 1024>>>();
    k_fill<<<(ETOT / 2 + 255) / 256, 256>>>(ei);

    {
        int nb = (NN * 2 * 32 + 255) / 256;
        k_agg4<6, true, 1><<<nb, 256>>>(bb[0]);
    }

    for (int l = 1; l < 4; l++) {
        dim3 gg(Fo[l] / 128, (NN + 127) / 128);
        k_gemm_tc<<<gg, 256, GEMM_SMEM>>>(nullptr, w16_base + woff[l],
                                          as_[l], ad_[l], NN, Fo[l], Fin[l], Cc[l]);
        if (l == 1) {
            int nb = (NN * 32 + 255) / 256;
            k_agg4<5, true, 0><<<nb, 256>>>(bb[l]);
        } else if (l == 2) {
            int nb = (NN * 32 + 255) / 256;
            k_agg2<true><<<nb, 256>>>(bb[l]);
        } else {
            int nb = (NN * 2 * 32 + 255) / 256;
            k_agg4<6, false, 1><<<nb, 256>>>(bb[l]);
        }
    }

    k_pool_init<<<(NN + 255) / 256, 256>>>();
    k_pool<<<(NN + POOL_CHUNK - 1) / POOL_CHUNK, 512>>>(batch);
    k_mlp1<<<(GMAX * 32 * 32 + 255) / 256, 256>>>(lw1, lb1);
    k_mlp2<<<1, 128>>>(lw2, lb2, out);
}